// round 3
// baseline (speedup 1.0000x reference)
#include <cuda_runtime.h>
#include <math.h>

// Problem constants
#define BSZ 8
#define SEQ 1024
#define DM  512
#define NH  8
#define HD  64
#define NEGV (-1e9f)

// Fused-attention tile config
#define ROWS 32          // q-rows per CTA
#define SP   1028        // P row stride (pad 4)
#define QS   68          // Qs row stride
#define BSTR 132         // Bs row stride
#define VSTR 68          // Vs row stride
// smem floats: P 32*1028 + union(Qs 32*68 + Bs 64*132 | Vs 32*68)
#define SMEM_FLOATS (ROWS*SP + ROWS*QS + 64*BSTR)
#define SMEM_BYTES  (SMEM_FLOATS * 4)

// ---------------------------------------------------------------------------
// Scratch
// ---------------------------------------------------------------------------
__device__ float g_q  [(size_t)BSZ * NH * SEQ * HD];   // [b,h,s,d]
__device__ float g_kT [(size_t)BSZ * NH * HD * SEQ];   // [b,h,d,s]
__device__ float g_v  [(size_t)BSZ * NH * SEQ * HD];   // [b,h,s,d]
__device__ float g_ctx[(size_t)BSZ * SEQ * DM];        // [b*s, h*dv]
__device__ float g_pre[(size_t)BSZ * SEQ * DM];        // pre-LN
__device__ float g_attn_fb[(size_t)BSZ * NH * SEQ * SEQ];

// ---------------------------------------------------------------------------
// Projection GEMM (unchanged from passing R2 kernel)
// ---------------------------------------------------------------------------
template<int MODE>
__global__ void __launch_bounds__(256)
gemm_proj(const float* __restrict__ A, const float* __restrict__ W,
          const float* __restrict__ bias, const float* __restrict__ resid,
          float* __restrict__ out)
{
    const int K = DM, N = DM;
    __shared__ float As[8][128];
    __shared__ float Bs[8][128];
    int tid = threadIdx.x;
    int tx = tid & 15, ty = tid >> 4;
    int m0 = blockIdx.y * 128, n0 = blockIdx.x * 128;

    float acc[8][8];
#pragma unroll
    for (int i = 0; i < 8; i++)
#pragma unroll
        for (int j = 0; j < 8; j++) acc[i][j] = 0.f;

    int a_row = tid >> 1, a_col = (tid & 1) * 4;
    int b_row = tid >> 5, b_col = (tid & 31) * 4;
    const float* Ag = A + (size_t)(m0 + a_row) * K + a_col;
    const float* Bg = W + (size_t)b_row * N + n0 + b_col;

    for (int k0 = 0; k0 < K; k0 += 8) {
        float4 av = *(const float4*)(Ag + k0);
        float4 bv = *(const float4*)(Bg + (size_t)k0 * N);
        As[a_col + 0][a_row] = av.x;
        As[a_col + 1][a_row] = av.y;
        As[a_col + 2][a_row] = av.z;
        As[a_col + 3][a_row] = av.w;
        *(float4*)&Bs[b_row][b_col] = bv;
        __syncthreads();
#pragma unroll
        for (int k = 0; k < 8; k++) {
            float a[8], b[8];
            *(float4*)(a)     = *(const float4*)&As[k][ty * 8];
            *(float4*)(a + 4) = *(const float4*)&As[k][ty * 8 + 4];
            *(float4*)(b)     = *(const float4*)&Bs[k][tx * 8];
            *(float4*)(b + 4) = *(const float4*)&Bs[k][tx * 8 + 4];
#pragma unroll
            for (int i = 0; i < 8; i++)
#pragma unroll
                for (int j = 0; j < 8; j++)
                    acc[i][j] = fmaf(a[i], b[j], acc[i][j]);
        }
        __syncthreads();
    }

#pragma unroll
    for (int i = 0; i < 8; i++) {
        int m = m0 + ty * 8 + i;
#pragma unroll
        for (int j = 0; j < 8; j++) {
            int n = n0 + tx * 8 + j;
            float v = acc[i][j] + bias[n];
            if (MODE == 2) {
                out[(size_t)m * DM + n] = v + resid[(size_t)m * DM + n];
            } else {
                int b_ = m >> 10, s = m & (SEQ - 1);
                int h  = n >> 6,  d = n & (HD - 1);
                if (MODE == 0)
                    out[(((size_t)(b_ * NH + h) * SEQ + s) << 6) + d] = v;
                else
                    out[(((size_t)(b_ * NH + h) * HD + d) << 10) + s] = v;
            }
        }
    }
}

// ---------------------------------------------------------------------------
// Fused attention: scores + scale + mask + adjoin + softmax + attn-write + ctx
// One CTA per (bh, 32 q-rows). P block (32x1024) kept in shared memory.
// ---------------------------------------------------------------------------
__global__ void __launch_bounds__(256, 1)
fused_attn(const float* __restrict__ q, const float* __restrict__ kT,
           const float* __restrict__ v, const int* __restrict__ mask,
           const float* __restrict__ adjoin,
           float* __restrict__ attn, float* __restrict__ ctx)
{
    extern __shared__ float sm[];
    float* P  = sm;                       // [32][1028]
    float* Qs = sm + ROWS * SP;           // [32][68]
    float* Bs = Qs + ROWS * QS;           // [64][132]
    float* Vs = Qs;                       // phase-3 alias over Qs/Bs region

    const int tid  = threadIdx.x;
    const int warp = tid >> 5, lane = tid & 31;
    const int bh = blockIdx.y;
    const int b_ = bh >> 3, h = bh & 7;
    const int q0 = blockIdx.x * ROWS;

    const float* qg = q  + ((size_t)bh * SEQ + q0) * HD;
    const float* kg = kT + (size_t)bh * HD * SEQ;
    const float* vg = v  + (size_t)bh * SEQ * HD;
    const int*   mrow = mask   + ((size_t)b_ * SEQ + q0) * SEQ;
    const float* arow = adjoin + ((size_t)b_ * SEQ + q0) * SEQ;

    // Stage Qs [32][64]
    {
        int r = tid >> 3, c4 = (tid & 7) * 8;
        float4 a0 = *(const float4*)(qg + (size_t)r * HD + c4);
        float4 a1 = *(const float4*)(qg + (size_t)r * HD + c4 + 4);
        *(float4*)&Qs[r * QS + c4]     = a0;
        *(float4*)&Qs[r * QS + c4 + 4] = a1;
    }

    const int r0 = warp * 4;   // 4 rows per warp in phase 1/2

    // ---------------- Phase 1: scores -> P ----------------
    for (int c = 0; c < 8; c++) {
        const int n0 = c * 128;
        __syncthreads();
        // stage Bs = kT[0:64][n0:n0+128]
#pragma unroll
        for (int j = 0; j < 8; j++) {
            int f = j * 256 + tid;            // float4 index, 2048 total
            int d = f >> 5;
            int cc = (f & 31) * 4;
            *(float4*)&Bs[d * BSTR + cc] =
                *(const float4*)(kg + (size_t)d * SEQ + n0 + cc);
        }
        __syncthreads();

        float acc[4][4];
#pragma unroll
        for (int i = 0; i < 4; i++)
#pragma unroll
            for (int j = 0; j < 4; j++) acc[i][j] = 0.f;

#pragma unroll
        for (int d0 = 0; d0 < 64; d0 += 4) {
            float a[4][4];
#pragma unroll
            for (int i = 0; i < 4; i++)
                *(float4*)a[i] = *(const float4*)&Qs[(r0 + i) * QS + d0];
#pragma unroll
            for (int dd = 0; dd < 4; dd++) {
                float b4[4];
                *(float4*)b4 = *(const float4*)&Bs[(d0 + dd) * BSTR + lane * 4];
#pragma unroll
                for (int i = 0; i < 4; i++)
#pragma unroll
                    for (int j = 0; j < 4; j++)
                        acc[i][j] = fmaf(a[i][dd], b4[j], acc[i][j]);
            }
        }

        // epilogue: scale, mask (before adjoin), +adjoin -> P
#pragma unroll
        for (int i = 0; i < 4; i++) {
            int row = r0 + i;
            size_t off = (size_t)row * SEQ + n0 + lane * 4;
            int4   m4 = *(const int4*)(mrow + off);
            float4 a4 = *(const float4*)(arow + off);
            float4 s;
            s.x = (m4.x ? NEGV : acc[i][0] * 0.125f) + a4.x;
            s.y = (m4.y ? NEGV : acc[i][1] * 0.125f) + a4.y;
            s.z = (m4.z ? NEGV : acc[i][2] * 0.125f) + a4.z;
            s.w = (m4.w ? NEGV : acc[i][3] * 0.125f) + a4.w;
            *(float4*)&P[row * SP + n0 + lane * 4] = s;
        }
    }
    __syncthreads();

    // ---------------- Phase 2: softmax in smem + write attn ----------------
    float* attn_base = attn + ((size_t)bh * SEQ + q0) * SEQ;
#pragma unroll
    for (int i = 0; i < 4; i++) {
        int row = r0 + i;
        float* pr = P + row * SP;
        float4 xv[8];
        float mx = -INFINITY;
#pragma unroll
        for (int j = 0; j < 8; j++) {
            xv[j] = *(const float4*)&pr[j * 128 + lane * 4];
            mx = fmaxf(mx, fmaxf(fmaxf(xv[j].x, xv[j].y), fmaxf(xv[j].z, xv[j].w)));
        }
#pragma unroll
        for (int o = 16; o; o >>= 1) mx = fmaxf(mx, __shfl_xor_sync(0xffffffffu, mx, o));
        float sum = 0.f;
#pragma unroll
        for (int j = 0; j < 8; j++) {
            xv[j].x = __expf(xv[j].x - mx); sum += xv[j].x;
            xv[j].y = __expf(xv[j].y - mx); sum += xv[j].y;
            xv[j].z = __expf(xv[j].z - mx); sum += xv[j].z;
            xv[j].w = __expf(xv[j].w - mx); sum += xv[j].w;
        }
#pragma unroll
        for (int o = 16; o; o >>= 1) sum += __shfl_xor_sync(0xffffffffu, sum, o);
        float inv = 1.f / sum;
        float* ar = attn_base + (size_t)row * SEQ;
#pragma unroll
        for (int j = 0; j < 8; j++) {
            float4 w;
            w.x = xv[j].x * inv; w.y = xv[j].y * inv;
            w.z = xv[j].z * inv; w.w = xv[j].w * inv;
            *(float4*)&pr[j * 128 + lane * 4] = w;
            *(float4*)&ar[j * 128 + lane * 4] = w;
        }
    }

    // ---------------- Phase 3: ctx = P @ V ----------------
    const int r  = tid >> 3;          // 0..31
    const int c0 = (tid & 7) * 8;     // 0..56
    float acc2[8];
#pragma unroll
    for (int j = 0; j < 8; j++) acc2[j] = 0.f;

    for (int k0 = 0; k0 < SEQ; k0 += 32) {
        __syncthreads();   // first iter: also phase2->3 barrier; later: guard Vs reuse
        // stage Vs = V[k0:k0+32][0:64]
#pragma unroll
        for (int j = 0; j < 2; j++) {
            int f = j * 256 + tid;           // float4 index, 512 total
            int kr = f >> 4;
            int cc = (f & 15) * 4;
            *(float4*)&Vs[kr * VSTR + cc] =
                *(const float4*)(vg + (size_t)(k0 + kr) * HD + cc);
        }
        __syncthreads();
#pragma unroll
        for (int k4 = 0; k4 < 32; k4 += 4) {
            float a4[4];
            *(float4*)a4 = *(const float4*)&P[r * SP + k0 + k4];
#pragma unroll
            for (int kk = 0; kk < 4; kk++) {
                float b8[8];
                *(float4*)(b8)     = *(const float4*)&Vs[(k4 + kk) * VSTR + c0];
                *(float4*)(b8 + 4) = *(const float4*)&Vs[(k4 + kk) * VSTR + c0 + 4];
#pragma unroll
                for (int j = 0; j < 8; j++)
                    acc2[j] = fmaf(a4[kk], b8[j], acc2[j]);
            }
        }
    }

    float* cr = ctx + ((size_t)(b_ * SEQ) + q0 + r) * DM + h * HD + c0;
    float4 w0, w1;
    w0.x = acc2[0]; w0.y = acc2[1]; w0.z = acc2[2]; w0.w = acc2[3];
    w1.x = acc2[4]; w1.y = acc2[5]; w1.z = acc2[6]; w1.w = acc2[7];
    *(float4*)(cr)     = w0;
    *(float4*)(cr + 4) = w1;
}

// ---------------------------------------------------------------------------
// LayerNorm
// ---------------------------------------------------------------------------
__global__ void __launch_bounds__(256)
layernorm_rows(const float* __restrict__ pre, const float* __restrict__ g,
               const float* __restrict__ be, float* __restrict__ out)
{
    int warp = threadIdx.x >> 5, lane = threadIdx.x & 31;
    size_t row = (size_t)blockIdx.x * 8 + warp;
    const float* p = pre + row * DM;

    float x[16];
    float s = 0.f, s2 = 0.f;
#pragma unroll
    for (int i = 0; i < 4; i++) {
        float4 v = *(const float4*)(p + i * 128 + lane * 4);
        x[i * 4 + 0] = v.x; x[i * 4 + 1] = v.y;
        x[i * 4 + 2] = v.z; x[i * 4 + 3] = v.w;
        s  += v.x + v.y + v.z + v.w;
        s2 += v.x * v.x + v.y * v.y + v.z * v.z + v.w * v.w;
    }
#pragma unroll
    for (int o = 16; o; o >>= 1) {
        s  += __shfl_xor_sync(0xffffffffu, s,  o);
        s2 += __shfl_xor_sync(0xffffffffu, s2, o);
    }
    float mu  = s  * (1.f / DM);
    float var = s2 * (1.f / DM) - mu * mu;
    float inv = rsqrtf(var + 1e-6f);

    float* po = out + row * DM;
#pragma unroll
    for (int i = 0; i < 4; i++) {
        float4 w;
        int c = i * 128 + lane * 4;
        w.x = (x[i * 4 + 0] - mu) * inv * g[c + 0] + be[c + 0];
        w.y = (x[i * 4 + 1] - mu) * inv * g[c + 1] + be[c + 1];
        w.z = (x[i * 4 + 2] - mu) * inv * g[c + 2] + be[c + 2];
        w.w = (x[i * 4 + 3] - mu) * inv * g[c + 3] + be[c + 3];
        *(float4*)(po + c) = w;
    }
}

// ---------------------------------------------------------------------------
// Launch
// ---------------------------------------------------------------------------
extern "C" void kernel_launch(void* const* d_in, const int* in_sizes, int n_in,
                              void* d_out, int out_size)
{
    const float* Q   = (const float*)d_in[0];
    const float* K   = (const float*)d_in[1];
    const float* V   = (const float*)d_in[2];
    const int*   mask = (const int*)d_in[3];   // bool materialized as int32
    const float* adjoin = (const float*)d_in[4];
    const float* Wq = (const float*)d_in[5];
    const float* bq = (const float*)d_in[6];
    const float* Wk = (const float*)d_in[7];
    const float* bk = (const float*)d_in[8];
    const float* Wv = (const float*)d_in[9];
    const float* bv = (const float*)d_in[10];
    const float* Wo = (const float*)d_in[11];
    const float* bo = (const float*)d_in[12];
    const float* lg = (const float*)d_in[13];
    const float* lb = (const float*)d_in[14];

    float *qb, *kb, *vb, *cb, *pb, *afb;
    cudaGetSymbolAddress((void**)&qb,  g_q);
    cudaGetSymbolAddress((void**)&kb,  g_kT);
    cudaGetSymbolAddress((void**)&vb,  g_v);
    cudaGetSymbolAddress((void**)&cb,  g_ctx);
    cudaGetSymbolAddress((void**)&pb,  g_pre);
    cudaGetSymbolAddress((void**)&afb, g_attn_fb);

    float* out0 = (float*)d_out;
    const size_t OUT0 = (size_t)BSZ * SEQ * DM;
    const size_t ATTN = (size_t)BSZ * NH * SEQ * SEQ;
    float* attn = ((size_t)out_size >= OUT0 + ATTN) ? (out0 + OUT0) : afb;

    static int smem_set = 0;
    if (!smem_set) {
        cudaFuncSetAttribute(fused_attn,
                             cudaFuncAttributeMaxDynamicSharedMemorySize,
                             SMEM_BYTES);
        smem_set = 1;
    }

    // 1) Projections
    dim3 gp(DM / 128, (BSZ * SEQ) / 128);
    gemm_proj<0><<<gp, 256>>>(Q, Wq, bq, nullptr, qb);
    gemm_proj<1><<<gp, 256>>>(K, Wk, bk, nullptr, kb);
    gemm_proj<0><<<gp, 256>>>(V, Wv, bv, nullptr, vb);

    // 2) Fused attention (scores+mask+adjoin+softmax+attn+ctx)
    dim3 ga(SEQ / ROWS, BSZ * NH);   // (32, 64)
    fused_attn<<<ga, 256, SMEM_BYTES>>>(qb, kb, vb, mask, adjoin, attn, cb);

    // 3) Output projection + bias + residual(Q)
    gemm_proj<2><<<gp, 256>>>(cb, Wo, bo, Q, pb);

    // 4) LayerNorm -> out
    layernorm_rows<<<(BSZ * SEQ) / 8, 256>>>(pb, lg, lb, out0);
}

// round 4
// speedup vs baseline: 1.8761x; 1.8761x over previous
#include <cuda_runtime.h>
#include <math.h>

// Problem constants
#define BSZ 8
#define SEQ 1024
#define DM  512
#define NH  8
#define HD  64
#define NEGV (-1e9f)

// ---------------------------------------------------------------------------
// Scratch
// ---------------------------------------------------------------------------
__device__ float g_q  [(size_t)BSZ * NH * SEQ * HD];   // [b,h,s,d]
__device__ float g_kT [(size_t)BSZ * NH * HD * SEQ];   // [b,h,d,s]
__device__ float g_v  [(size_t)BSZ * NH * SEQ * HD];   // [b,h,s,d]
__device__ float g_ctx[(size_t)BSZ * SEQ * DM];        // [b*s, h*dv]
__device__ float g_pre[(size_t)BSZ * SEQ * DM];        // pre-LN
__device__ float g_attn_fb[(size_t)BSZ * NH * SEQ * SEQ];

// ---------------------------------------------------------------------------
// Projection GEMM: C = A[M,K] @ W[K,N] + bias, M=8192, N=K=512 (as in R2)
// ---------------------------------------------------------------------------
template<int MODE>
__global__ void __launch_bounds__(256)
gemm_proj(const float* __restrict__ A, const float* __restrict__ W,
          const float* __restrict__ bias, const float* __restrict__ resid,
          float* __restrict__ out)
{
    const int K = DM, N = DM;
    __shared__ float As[8][128];
    __shared__ float Bs[8][128];
    int tid = threadIdx.x;
    int tx = tid & 15, ty = tid >> 4;
    int m0 = blockIdx.y * 128, n0 = blockIdx.x * 128;

    float acc[8][8];
#pragma unroll
    for (int i = 0; i < 8; i++)
#pragma unroll
        for (int j = 0; j < 8; j++) acc[i][j] = 0.f;

    int a_row = tid >> 1, a_col = (tid & 1) * 4;
    int b_row = tid >> 5, b_col = (tid & 31) * 4;
    const float* Ag = A + (size_t)(m0 + a_row) * K + a_col;
    const float* Bg = W + (size_t)b_row * N + n0 + b_col;

    for (int k0 = 0; k0 < K; k0 += 8) {
        float4 av = *(const float4*)(Ag + k0);
        float4 bv = *(const float4*)(Bg + (size_t)k0 * N);
        As[a_col + 0][a_row] = av.x;
        As[a_col + 1][a_row] = av.y;
        As[a_col + 2][a_row] = av.z;
        As[a_col + 3][a_row] = av.w;
        *(float4*)&Bs[b_row][b_col] = bv;
        __syncthreads();
#pragma unroll
        for (int k = 0; k < 8; k++) {
            float a[8], b[8];
            *(float4*)(a)     = *(const float4*)&As[k][ty * 8];
            *(float4*)(a + 4) = *(const float4*)&As[k][ty * 8 + 4];
            *(float4*)(b)     = *(const float4*)&Bs[k][tx * 8];
            *(float4*)(b + 4) = *(const float4*)&Bs[k][tx * 8 + 4];
#pragma unroll
            for (int i = 0; i < 8; i++)
#pragma unroll
                for (int j = 0; j < 8; j++)
                    acc[i][j] = fmaf(a[i], b[j], acc[i][j]);
        }
        __syncthreads();
    }

#pragma unroll
    for (int i = 0; i < 8; i++) {
        int m = m0 + ty * 8 + i;
#pragma unroll
        for (int j = 0; j < 8; j++) {
            int n = n0 + tx * 8 + j;
            float v = acc[i][j] + bias[n];
            if (MODE == 2) {
                out[(size_t)m * DM + n] = v + resid[(size_t)m * DM + n];
            } else {
                int b_ = m >> 10, s = m & (SEQ - 1);
                int h  = n >> 6,  d = n & (HD - 1);
                if (MODE == 0)
                    out[(((size_t)(b_ * NH + h) * SEQ + s) << 6) + d] = v;
                else
                    out[(((size_t)(b_ * NH + h) * HD + d) << 10) + s] = v;
            }
        }
    }
}

// ---------------------------------------------------------------------------
// Score GEMM v2: K=64 fully resident in smem -> ONE barrier, then a
// 64-deep uninterrupted FMA loop. 128x128 tile, 256 threads, 8x8 micro.
// Epilogue: scale, mask (int32, BEFORE adjoin), +adjoin.
// Dynamic smem: As[64][128] + Bs[64][128] = 64KB.
// ---------------------------------------------------------------------------
#define SC_SMEM (2 * 64 * 128 * 4)
__global__ void __launch_bounds__(256)
gemm_scores2(const float* __restrict__ q, const float* __restrict__ kT,
             const int* __restrict__ mask,
             const float* __restrict__ adjoin,
             float* __restrict__ scores)
{
    extern __shared__ float sm[];
    float* As = sm;              // [64][128]  (d-major, m inner)
    float* Bs = sm + 64 * 128;   // [64][128]  (d-major, n inner)

    const int bh = blockIdx.z;
    const int b_ = bh >> 3;
    const float* A  = q  + (size_t)bh * SEQ * HD;
    const float* Bm = kT + (size_t)bh * HD * SEQ;
    float* out = scores + (size_t)bh * SEQ * SEQ;

    const int tid = threadIdx.x;
    const int tx = tid & 15, ty = tid >> 4;
    const int m0 = blockIdx.y * 128, n0 = blockIdx.x * 128;

    // Load full panels
    const int a_row = tid >> 1, a_col = (tid & 1) * 4;   // A: 128 rows x 8 d per pass
    const int b_row = tid >> 5, b_col = (tid & 31) * 4;  // B: 8 d x 128 n per pass
#pragma unroll
    for (int j = 0; j < 8; j++) {
        int d0 = j * 8;
        float4 av = *(const float4*)(A + (size_t)(m0 + a_row) * HD + d0 + a_col);
        As[(d0 + a_col + 0) * 128 + a_row] = av.x;
        As[(d0 + a_col + 1) * 128 + a_row] = av.y;
        As[(d0 + a_col + 2) * 128 + a_row] = av.z;
        As[(d0 + a_col + 3) * 128 + a_row] = av.w;
        float4 bv = *(const float4*)(Bm + (size_t)(d0 + b_row) * SEQ + n0 + b_col);
        *(float4*)&Bs[(d0 + b_row) * 128 + b_col] = bv;
    }
    __syncthreads();

    float acc[8][8];
#pragma unroll
    for (int i = 0; i < 8; i++)
#pragma unroll
        for (int j = 0; j < 8; j++) acc[i][j] = 0.f;

#pragma unroll 8
    for (int d = 0; d < 64; d++) {
        float a[8], b[8];
        *(float4*)(a)     = *(const float4*)&As[d * 128 + ty * 8];
        *(float4*)(a + 4) = *(const float4*)&As[d * 128 + ty * 8 + 4];
        *(float4*)(b)     = *(const float4*)&Bs[d * 128 + tx * 8];
        *(float4*)(b + 4) = *(const float4*)&Bs[d * 128 + tx * 8 + 4];
#pragma unroll
        for (int i = 0; i < 8; i++)
#pragma unroll
            for (int j = 0; j < 8; j++)
                acc[i][j] = fmaf(a[i], b[j], acc[i][j]);
    }

    const int*   mb = mask   + (size_t)b_ * SEQ * SEQ;
    const float* ab = adjoin + (size_t)b_ * SEQ * SEQ;
#pragma unroll
    for (int i = 0; i < 8; i++) {
        int m = m0 + ty * 8 + i;
        size_t roff = (size_t)m * SEQ;
#pragma unroll
        for (int j = 0; j < 8; j += 4) {
            int n = n0 + tx * 8 + j;
            int4   m4 = *(const int4*)(mb + roff + n);
            float4 a4 = *(const float4*)(ab + roff + n);
            float4 s;
            s.x = (m4.x ? NEGV : acc[i][j + 0] * 0.125f) + a4.x;
            s.y = (m4.y ? NEGV : acc[i][j + 1] * 0.125f) + a4.y;
            s.z = (m4.z ? NEGV : acc[i][j + 2] * 0.125f) + a4.z;
            s.w = (m4.w ? NEGV : acc[i][j + 3] * 0.125f) + a4.w;
            *(float4*)(out + roff + n) = s;
        }
    }
}

// ---------------------------------------------------------------------------
// Softmax: one warp per row of 1024, in place (as in R2).
// ---------------------------------------------------------------------------
__global__ void __launch_bounds__(256)
softmax_rows(float* __restrict__ scores)
{
    int warp = threadIdx.x >> 5, lane = threadIdx.x & 31;
    size_t row = (size_t)blockIdx.x * 8 + warp;
    float* p = scores + row * SEQ;

    float x[32];
    float mx = -INFINITY;
#pragma unroll
    for (int i = 0; i < 8; i++) {
        float4 v = *(const float4*)(p + i * 128 + lane * 4);
        x[i * 4 + 0] = v.x; x[i * 4 + 1] = v.y;
        x[i * 4 + 2] = v.z; x[i * 4 + 3] = v.w;
        mx = fmaxf(mx, fmaxf(fmaxf(v.x, v.y), fmaxf(v.z, v.w)));
    }
#pragma unroll
    for (int o = 16; o; o >>= 1) mx = fmaxf(mx, __shfl_xor_sync(0xffffffffu, mx, o));

    float sum = 0.f;
#pragma unroll
    for (int i = 0; i < 32; i++) { x[i] = __expf(x[i] - mx); sum += x[i]; }
#pragma unroll
    for (int o = 16; o; o >>= 1) sum += __shfl_xor_sync(0xffffffffu, sum, o);

    float inv = 1.f / sum;
#pragma unroll
    for (int i = 0; i < 8; i++) {
        float4 v;
        v.x = x[i * 4 + 0] * inv; v.y = x[i * 4 + 1] * inv;
        v.z = x[i * 4 + 2] * inv; v.w = x[i * 4 + 3] * inv;
        *(float4*)(p + i * 128 + lane * 4) = v;
    }
}

// ---------------------------------------------------------------------------
// Context GEMM v2: ctx = attn[1024,1024] @ v[1024,64]; k-chunk 64
// (4x fewer barriers than R2). 128x64 tile, 256 threads, 8x4 micro.
// Dynamic smem: As[64][128] (k-major) + Vs[64][68] = 49KB.
// ---------------------------------------------------------------------------
#define VSTR2 68
#define CT_SMEM ((64 * 128 + 64 * VSTR2) * 4)
__global__ void __launch_bounds__(256)
gemm_ctx2(const float* __restrict__ attn, const float* __restrict__ v,
          float* __restrict__ ctx)
{
    extern __shared__ float sm[];
    float* As = sm;              // [64][128]  (k-major, m inner)
    float* Vs = sm + 64 * 128;   // [64][68]

    const int bh = blockIdx.z;
    const int b_ = bh >> 3, h = bh & 7;
    const float* A  = attn + (size_t)bh * SEQ * SEQ;
    const float* Bm = v    + (size_t)bh * SEQ * HD;
    const int m0 = blockIdx.y * 128;

    const int tid = threadIdx.x;
    const int tx = tid & 15, ty = tid >> 4;

    float acc[8][4];
#pragma unroll
    for (int i = 0; i < 8; i++)
#pragma unroll
        for (int j = 0; j < 4; j++) acc[i][j] = 0.f;

    const int a_row = tid >> 1, a_col = (tid & 1) * 4;

    for (int k0 = 0; k0 < SEQ; k0 += 64) {
        __syncthreads();
        // A panel: 128 m x 64 k, transposed into As[k][m]
#pragma unroll
        for (int j = 0; j < 8; j++) {
            int kk = j * 8 + a_col;
            float4 av = *(const float4*)(A + (size_t)(m0 + a_row) * SEQ + k0 + kk);
            As[(kk + 0) * 128 + a_row] = av.x;
            As[(kk + 1) * 128 + a_row] = av.y;
            As[(kk + 2) * 128 + a_row] = av.z;
            As[(kk + 3) * 128 + a_row] = av.w;
        }
        // V panel: 64 k x 64 n
#pragma unroll
        for (int j = 0; j < 4; j++) {
            int f = j * 256 + tid;          // 1024 float4 total
            int kr = f >> 4, cc = (f & 15) * 4;
            *(float4*)&Vs[kr * VSTR2 + cc] =
                *(const float4*)(Bm + (size_t)(k0 + kr) * HD + cc);
        }
        __syncthreads();
#pragma unroll 8
        for (int k = 0; k < 64; k++) {
            float a[8], bb[4];
            *(float4*)(a)     = *(const float4*)&As[k * 128 + ty * 8];
            *(float4*)(a + 4) = *(const float4*)&As[k * 128 + ty * 8 + 4];
            *(float4*)(bb)    = *(const float4*)&Vs[k * VSTR2 + tx * 4];
#pragma unroll
            for (int i = 0; i < 8; i++)
#pragma unroll
                for (int j = 0; j < 4; j++)
                    acc[i][j] = fmaf(a[i], bb[j], acc[i][j]);
        }
    }

#pragma unroll
    for (int i = 0; i < 8; i++) {
        int m = m0 + ty * 8 + i;
        float4 w;
        w.x = acc[i][0]; w.y = acc[i][1]; w.z = acc[i][2]; w.w = acc[i][3];
        *(float4*)&ctx[((size_t)(b_ * SEQ + m)) * DM + h * HD + tx * 4] = w;
    }
}

// ---------------------------------------------------------------------------
// LayerNorm
// ---------------------------------------------------------------------------
__global__ void __launch_bounds__(256)
layernorm_rows(const float* __restrict__ pre, const float* __restrict__ g,
               const float* __restrict__ be, float* __restrict__ out)
{
    int warp = threadIdx.x >> 5, lane = threadIdx.x & 31;
    size_t row = (size_t)blockIdx.x * 8 + warp;
    const float* p = pre + row * DM;

    float x[16];
    float s = 0.f, s2 = 0.f;
#pragma unroll
    for (int i = 0; i < 4; i++) {
        float4 v = *(const float4*)(p + i * 128 + lane * 4);
        x[i * 4 + 0] = v.x; x[i * 4 + 1] = v.y;
        x[i * 4 + 2] = v.z; x[i * 4 + 3] = v.w;
        s  += v.x + v.y + v.z + v.w;
        s2 += v.x * v.x + v.y * v.y + v.z * v.z + v.w * v.w;
    }
#pragma unroll
    for (int o = 16; o; o >>= 1) {
        s  += __shfl_xor_sync(0xffffffffu, s,  o);
        s2 += __shfl_xor_sync(0xffffffffu, s2, o);
    }
    float mu  = s  * (1.f / DM);
    float var = s2 * (1.f / DM) - mu * mu;
    float inv = rsqrtf(var + 1e-6f);

    float* po = out + row * DM;
#pragma unroll
    for (int i = 0; i < 4; i++) {
        float4 w;
        int c = i * 128 + lane * 4;
        w.x = (x[i * 4 + 0] - mu) * inv * g[c + 0] + be[c + 0];
        w.y = (x[i * 4 + 1] - mu) * inv * g[c + 1] + be[c + 1];
        w.z = (x[i * 4 + 2] - mu) * inv * g[c + 2] + be[c + 2];
        w.w = (x[i * 4 + 3] - mu) * inv * g[c + 3] + be[c + 3];
        *(float4*)(po + c) = w;
    }
}

// ---------------------------------------------------------------------------
// Launch
// ---------------------------------------------------------------------------
extern "C" void kernel_launch(void* const* d_in, const int* in_sizes, int n_in,
                              void* d_out, int out_size)
{
    const float* Q   = (const float*)d_in[0];
    const float* K   = (const float*)d_in[1];
    const float* V   = (const float*)d_in[2];
    const int*   mask = (const int*)d_in[3];   // bool materialized as int32
    const float* adjoin = (const float*)d_in[4];
    const float* Wq = (const float*)d_in[5];
    const float* bq = (const float*)d_in[6];
    const float* Wk = (const float*)d_in[7];
    const float* bk = (const float*)d_in[8];
    const float* Wv = (const float*)d_in[9];
    const float* bv = (const float*)d_in[10];
    const float* Wo = (const float*)d_in[11];
    const float* bo = (const float*)d_in[12];
    const float* lg = (const float*)d_in[13];
    const float* lb = (const float*)d_in[14];

    float *qb, *kb, *vb, *cb, *pb, *afb;
    cudaGetSymbolAddress((void**)&qb,  g_q);
    cudaGetSymbolAddress((void**)&kb,  g_kT);
    cudaGetSymbolAddress((void**)&vb,  g_v);
    cudaGetSymbolAddress((void**)&cb,  g_ctx);
    cudaGetSymbolAddress((void**)&pb,  g_pre);
    cudaGetSymbolAddress((void**)&afb, g_attn_fb);

    float* out0 = (float*)d_out;
    const size_t OUT0 = (size_t)BSZ * SEQ * DM;
    const size_t ATTN = (size_t)BSZ * NH * SEQ * SEQ;
    float* attn = ((size_t)out_size >= OUT0 + ATTN) ? (out0 + OUT0) : afb;

    static int attr_set = 0;
    if (!attr_set) {
        cudaFuncSetAttribute(gemm_scores2,
                             cudaFuncAttributeMaxDynamicSharedMemorySize, SC_SMEM);
        cudaFuncSetAttribute(gemm_ctx2,
                             cudaFuncAttributeMaxDynamicSharedMemorySize, CT_SMEM);
        attr_set = 1;
    }

    // 1) Projections (q, v in [b,h,s,d]; k transposed to [b,h,d,s])
    dim3 gp(DM / 128, (BSZ * SEQ) / 128);
    gemm_proj<0><<<gp, 256>>>(Q, Wq, bq, nullptr, qb);
    gemm_proj<1><<<gp, 256>>>(K, Wk, bk, nullptr, kb);
    gemm_proj<0><<<gp, 256>>>(V, Wv, bv, nullptr, vb);

    // 2) Scores + scale + mask + adjoin (barrier-free mainloop)
    dim3 gs(SEQ / 128, SEQ / 128, BSZ * NH);
    gemm_scores2<<<gs, 256, SC_SMEM>>>(qb, kb, mask, adjoin, attn);

    // 3) Softmax in place
    softmax_rows<<<(BSZ * NH * SEQ) / 8, 256>>>(attn);

    // 4) Context
    dim3 gc(1, SEQ / 128, BSZ * NH);
    gemm_ctx2<<<gc, 256, CT_SMEM>>>(attn, vb, cb);

    // 5) Output projection + bias + residual(Q)
    gemm_proj<2><<<gp, 256>>>(cb, Wo, bo, Q, pb);

    // 6) LayerNorm -> out
    layernorm_rows<<<(BSZ * SEQ) / 8, 256>>>(pb, lg, lb, out0);
}

// round 6
// speedup vs baseline: 1.9307x; 1.0291x over previous
#include <cuda_runtime.h>
#include <cuda_bf16.h>
#include <math.h>
#include <stdint.h>

// Problem constants
#define BSZ 8
#define SEQ 1024
#define DM  512
#define NH  8
#define HD  64
#define NEGV (-1e9f)

// ---------------------------------------------------------------------------
// Scratch
// ---------------------------------------------------------------------------
__device__ float g_q  [(size_t)BSZ * NH * SEQ * HD];   // [b,h,s,d]
__device__ float g_kT [(size_t)BSZ * NH * HD * SEQ];   // [b,h,d,s]
__device__ float g_v  [(size_t)BSZ * NH * SEQ * HD];   // [b,h,s,d]
__device__ float g_ctx[(size_t)BSZ * SEQ * DM];        // [b*s, h*dv]
__device__ float g_pre[(size_t)BSZ * SEQ * DM];        // pre-LN
__device__ float g_attn_fb[(size_t)BSZ * NH * SEQ * SEQ];

// ===========================================================================
// mma.sync bf16 helpers (legacy HMMA path — valid on plain sm_103 target)
// ===========================================================================
__device__ __forceinline__ void mma_bf16(float* d, const uint32_t* a,
                                         uint32_t b0, uint32_t b1)
{
    asm volatile(
        "mma.sync.aligned.m16n8k16.row.col.f32.bf16.bf16.f32 "
        "{%0,%1,%2,%3}, {%4,%5,%6,%7}, {%8,%9}, {%0,%1,%2,%3};"
        : "+f"(d[0]), "+f"(d[1]), "+f"(d[2]), "+f"(d[3])
        : "r"(a[0]), "r"(a[1]), "r"(a[2]), "r"(a[3]), "r"(b0), "r"(b1));
}

__device__ __forceinline__ uint32_t pack_hi(float x, float y) {
    __nv_bfloat162 p = __halves2bfloat162(__float2bfloat16(x), __float2bfloat16(y));
    return *(uint32_t*)&p;
}
__device__ __forceinline__ uint32_t pack_lo(float x, float y) {
    __nv_bfloat16 hx = __float2bfloat16(x), hy = __float2bfloat16(y);
    __nv_bfloat162 p = __halves2bfloat162(
        __float2bfloat16(x - __bfloat162float(hx)),
        __float2bfloat16(y - __bfloat162float(hy)));
    return *(uint32_t*)&p;
}

// smem panels: Ah/Al [128 m][72 k] bf16, Bh/Bl [128 n][72 k] bf16
#define PSTR 72
#define PANEL (128 * PSTR)                 // bf16 elements
#define PROJ_SMEM (4 * PANEL * 2)          // 73728 bytes

// ===========================================================================
// Tensor-core projection GEMM via mma.sync: C = A[8192,512] @ W[512,512] + bias
// bf16 split (hi/lo), fp32 accum: acc += Ah*Bh + Ah*Bl + Al*Bh.
// 128x128 tile, 8 warps (64x32 each), K-chunks of 64.
// MODE 0: scatter [b,h,s,d]; MODE 1: scatter [b,h,d,s]; MODE 2: +resid row-major
// ===========================================================================
template<int MODE>
__global__ void __launch_bounds__(256)
gemm_proj_mma(const float* __restrict__ A, const float* __restrict__ W,
              const float* __restrict__ bias, const float* __restrict__ resid,
              float* __restrict__ out)
{
    extern __shared__ __nv_bfloat16 sb[];
    __nv_bfloat16* Ah = sb;
    __nv_bfloat16* Al = Ah + PANEL;
    __nv_bfloat16* Bh = Al + PANEL;
    __nv_bfloat16* Bl = Bh + PANEL;

    const int tid = threadIdx.x, wid = tid >> 5, lane = tid & 31;
    const int m0 = blockIdx.y * 128, n0 = blockIdx.x * 128;
    const int wm = (wid >> 2) * 64;     // warp row base (0 / 64)
    const int wn = (wid & 3) * 32;      // warp col base (0/32/64/96)
    const int lg = lane >> 2;           // group id 0..7
    const int lq = lane & 3;            // quad lane 0..3

    float acc[4][4][4];
#pragma unroll
    for (int i = 0; i < 4; i++)
#pragma unroll
        for (int j = 0; j < 4; j++)
#pragma unroll
            for (int r = 0; r < 4; r++) acc[i][j][r] = 0.f;

    const int ar  = tid >> 1;           // A stage row 0..127
    const int ac4 = (tid & 1) * 8;      // starting float4 within row

    for (int kc = 0; kc < 8; kc++) {
        const int k0 = kc * 64;
        __syncthreads();
        // ---- stage A [128 m][64 k] -> hi/lo
#pragma unroll
        for (int j = 0; j < 8; j++) {
            int c = (ac4 + j) * 4;
            float4 v = *(const float4*)(A + (size_t)(m0 + ar) * DM + k0 + c);
            *(uint32_t*)&Ah[ar * PSTR + c]     = pack_hi(v.x, v.y);
            *(uint32_t*)&Ah[ar * PSTR + c + 2] = pack_hi(v.z, v.w);
            *(uint32_t*)&Al[ar * PSTR + c]     = pack_lo(v.x, v.y);
            *(uint32_t*)&Al[ar * PSTR + c + 2] = pack_lo(v.z, v.w);
        }
        // ---- stage B: W[k0+k][n0+n] -> Bs[n][k] hi/lo (transpose)
#pragma unroll
        for (int j = 0; j < 8; j++) {
            int f = j * 256 + tid;              // 2048 float4
            int kk = f >> 5, n4 = (f & 31) * 4;
            float4 w4 = *(const float4*)(W + (size_t)(k0 + kk) * DM + n0 + n4);
            const float wv[4] = {w4.x, w4.y, w4.z, w4.w};
#pragma unroll
            for (int e = 0; e < 4; e++) {
                __nv_bfloat16 h = __float2bfloat16(wv[e]);
                Bh[(n4 + e) * PSTR + kk] = h;
                Bl[(n4 + e) * PSTR + kk] =
                    __float2bfloat16(wv[e] - __bfloat162float(h));
            }
        }
        __syncthreads();

        // ---- compute: 4 k-steps of 16
#pragma unroll
        for (int ks = 0; ks < 4; ks++) {
            const int kb = ks * 16;
            uint32_t ah[4][4], al[4][4];
#pragma unroll
            for (int i = 0; i < 4; i++) {
                int r = wm + i * 16 + lg;
                int c = kb + lq * 2;
                ah[i][0] = *(const uint32_t*)&Ah[r * PSTR + c];
                ah[i][1] = *(const uint32_t*)&Ah[(r + 8) * PSTR + c];
                ah[i][2] = *(const uint32_t*)&Ah[r * PSTR + c + 8];
                ah[i][3] = *(const uint32_t*)&Ah[(r + 8) * PSTR + c + 8];
                al[i][0] = *(const uint32_t*)&Al[r * PSTR + c];
                al[i][1] = *(const uint32_t*)&Al[(r + 8) * PSTR + c];
                al[i][2] = *(const uint32_t*)&Al[r * PSTR + c + 8];
                al[i][3] = *(const uint32_t*)&Al[(r + 8) * PSTR + c + 8];
            }
#pragma unroll
            for (int j = 0; j < 4; j++) {
                int n = wn + j * 8 + lg;
                int ck = kb + lq * 2;
                uint32_t bh0 = *(const uint32_t*)&Bh[n * PSTR + ck];
                uint32_t bh1 = *(const uint32_t*)&Bh[n * PSTR + ck + 8];
                uint32_t bl0 = *(const uint32_t*)&Bl[n * PSTR + ck];
                uint32_t bl1 = *(const uint32_t*)&Bl[n * PSTR + ck + 8];
#pragma unroll
                for (int i = 0; i < 4; i++) {
                    mma_bf16(acc[i][j], ah[i], bh0, bh1);
                    mma_bf16(acc[i][j], ah[i], bl0, bl1);
                    mma_bf16(acc[i][j], al[i], bh0, bh1);
                }
            }
        }
    }

    // ---- epilogue: D frag (r, c),(r, c+1),(r+8, c),(r+8, c+1)
#pragma unroll
    for (int i = 0; i < 4; i++) {
        int r1 = m0 + wm + i * 16 + lg;
        int r2 = r1 + 8;
#pragma unroll
        for (int j = 0; j < 4; j++) {
            int n = n0 + wn + j * 8 + lq * 2;
            float b0 = bias[n], b1 = bias[n + 1];
            float v00 = acc[i][j][0] + b0, v01 = acc[i][j][1] + b1;
            float v10 = acc[i][j][2] + b0, v11 = acc[i][j][3] + b1;
            if (MODE == 2) {
                float2 q1 = *(const float2*)(resid + (size_t)r1 * DM + n);
                float2 q2 = *(const float2*)(resid + (size_t)r2 * DM + n);
                float2 o1 = {v00 + q1.x, v01 + q1.y};
                float2 o2 = {v10 + q2.x, v11 + q2.y};
                *(float2*)(out + (size_t)r1 * DM + n) = o1;
                *(float2*)(out + (size_t)r2 * DM + n) = o2;
            } else if (MODE == 0) {
                int h = n >> 6, d = n & (HD - 1);
                int b1_ = r1 >> 10, s1 = r1 & (SEQ - 1);
                int b2_ = r2 >> 10, s2 = r2 & (SEQ - 1);
                float2 o1 = {v00, v01};
                float2 o2 = {v10, v11};
                *(float2*)(out + (((size_t)(b1_ * NH + h) * SEQ + s1) << 6) + d) = o1;
                *(float2*)(out + (((size_t)(b2_ * NH + h) * SEQ + s2) << 6) + d) = o2;
            } else {
                int h = n >> 6, d = n & (HD - 1);
                int b1_ = r1 >> 10, s1 = r1 & (SEQ - 1);
                int b2_ = r2 >> 10, s2 = r2 & (SEQ - 1);
                out[(((size_t)(b1_ * NH + h) * HD + d)     << 10) + s1] = v00;
                out[(((size_t)(b1_ * NH + h) * HD + d + 1) << 10) + s1] = v01;
                out[(((size_t)(b2_ * NH + h) * HD + d)     << 10) + s2] = v10;
                out[(((size_t)(b2_ * NH + h) * HD + d + 1) << 10) + s2] = v11;
            }
        }
    }
}

// ===========================================================================
// Attention path — identical to R4 (proven)
// ===========================================================================
#define SC_SMEM (2 * 64 * 128 * 4)
__global__ void __launch_bounds__(256)
gemm_scores2(const float* __restrict__ q, const float* __restrict__ kT,
             const int* __restrict__ mask,
             const float* __restrict__ adjoin,
             float* __restrict__ scores)
{
    extern __shared__ float sm[];
    float* As = sm;
    float* Bs = sm + 64 * 128;

    const int bh = blockIdx.z;
    const int b_ = bh >> 3;
    const float* A  = q  + (size_t)bh * SEQ * HD;
    const float* Bm = kT + (size_t)bh * HD * SEQ;
    float* out = scores + (size_t)bh * SEQ * SEQ;

    const int tid = threadIdx.x;
    const int tx = tid & 15, ty = tid >> 4;
    const int m0 = blockIdx.y * 128, n0 = blockIdx.x * 128;

    const int a_row = tid >> 1, a_col = (tid & 1) * 4;
    const int b_row = tid >> 5, b_col = (tid & 31) * 4;
#pragma unroll
    for (int j = 0; j < 8; j++) {
        int d0 = j * 8;
        float4 av = *(const float4*)(A + (size_t)(m0 + a_row) * HD + d0 + a_col);
        As[(d0 + a_col + 0) * 128 + a_row] = av.x;
        As[(d0 + a_col + 1) * 128 + a_row] = av.y;
        As[(d0 + a_col + 2) * 128 + a_row] = av.z;
        As[(d0 + a_col + 3) * 128 + a_row] = av.w;
        float4 bv = *(const float4*)(Bm + (size_t)(d0 + b_row) * SEQ + n0 + b_col);
        *(float4*)&Bs[(d0 + b_row) * 128 + b_col] = bv;
    }
    __syncthreads();

    float acc[8][8];
#pragma unroll
    for (int i = 0; i < 8; i++)
#pragma unroll
        for (int j = 0; j < 8; j++) acc[i][j] = 0.f;

#pragma unroll 8
    for (int d = 0; d < 64; d++) {
        float a[8], b[8];
        *(float4*)(a)     = *(const float4*)&As[d * 128 + ty * 8];
        *(float4*)(a + 4) = *(const float4*)&As[d * 128 + ty * 8 + 4];
        *(float4*)(b)     = *(const float4*)&Bs[d * 128 + tx * 8];
        *(float4*)(b + 4) = *(const float4*)&Bs[d * 128 + tx * 8 + 4];
#pragma unroll
        for (int i = 0; i < 8; i++)
#pragma unroll
            for (int j = 0; j < 8; j++)
                acc[i][j] = fmaf(a[i], b[j], acc[i][j]);
    }

    const int*   mb = mask   + (size_t)b_ * SEQ * SEQ;
    const float* ab = adjoin + (size_t)b_ * SEQ * SEQ;
#pragma unroll
    for (int i = 0; i < 8; i++) {
        int m = m0 + ty * 8 + i;
        size_t roff = (size_t)m * SEQ;
#pragma unroll
        for (int j = 0; j < 8; j += 4) {
            int n = n0 + tx * 8 + j;
            int4   m4 = *(const int4*)(mb + roff + n);
            float4 a4 = *(const float4*)(ab + roff + n);
            float4 s;
            s.x = (m4.x ? NEGV : acc[i][j + 0] * 0.125f) + a4.x;
            s.y = (m4.y ? NEGV : acc[i][j + 1] * 0.125f) + a4.y;
            s.z = (m4.z ? NEGV : acc[i][j + 2] * 0.125f) + a4.z;
            s.w = (m4.w ? NEGV : acc[i][j + 3] * 0.125f) + a4.w;
            *(float4*)(out + roff + n) = s;
        }
    }
}

__global__ void __launch_bounds__(256)
softmax_rows(float* __restrict__ scores)
{
    int warp = threadIdx.x >> 5, lane = threadIdx.x & 31;
    size_t row = (size_t)blockIdx.x * 8 + warp;
    float* p = scores + row * SEQ;

    float x[32];
    float mx = -INFINITY;
#pragma unroll
    for (int i = 0; i < 8; i++) {
        float4 v = *(const float4*)(p + i * 128 + lane * 4);
        x[i * 4 + 0] = v.x; x[i * 4 + 1] = v.y;
        x[i * 4 + 2] = v.z; x[i * 4 + 3] = v.w;
        mx = fmaxf(mx, fmaxf(fmaxf(v.x, v.y), fmaxf(v.z, v.w)));
    }
#pragma unroll
    for (int o = 16; o; o >>= 1) mx = fmaxf(mx, __shfl_xor_sync(0xffffffffu, mx, o));

    float sum = 0.f;
#pragma unroll
    for (int i = 0; i < 32; i++) { x[i] = __expf(x[i] - mx); sum += x[i]; }
#pragma unroll
    for (int o = 16; o; o >>= 1) sum += __shfl_xor_sync(0xffffffffu, sum, o);

    float inv = 1.f / sum;
#pragma unroll
    for (int i = 0; i < 8; i++) {
        float4 v;
        v.x = x[i * 4 + 0] * inv; v.y = x[i * 4 + 1] * inv;
        v.z = x[i * 4 + 2] * inv; v.w = x[i * 4 + 3] * inv;
        *(float4*)(p + i * 128 + lane * 4) = v;
    }
}

#define VSTR2 68
#define CT_SMEM ((64 * 128 + 64 * VSTR2) * 4)
__global__ void __launch_bounds__(256)
gemm_ctx2(const float* __restrict__ attn, const float* __restrict__ v,
          float* __restrict__ ctx)
{
    extern __shared__ float sm[];
    float* As = sm;
    float* Vs = sm + 64 * 128;

    const int bh = blockIdx.z;
    const int b_ = bh >> 3, h = bh & 7;
    const float* A  = attn + (size_t)bh * SEQ * SEQ;
    const float* Bm = v    + (size_t)bh * SEQ * HD;
    const int m0 = blockIdx.y * 128;

    const int tid = threadIdx.x;
    const int tx = tid & 15, ty = tid >> 4;

    float acc[8][4];
#pragma unroll
    for (int i = 0; i < 8; i++)
#pragma unroll
        for (int j = 0; j < 4; j++) acc[i][j] = 0.f;

    const int a_row = tid >> 1, a_col = (tid & 1) * 4;

    for (int k0 = 0; k0 < SEQ; k0 += 64) {
        __syncthreads();
#pragma unroll
        for (int j = 0; j < 8; j++) {
            int kk = j * 8 + a_col;
            float4 av = *(const float4*)(A + (size_t)(m0 + a_row) * SEQ + k0 + kk);
            As[(kk + 0) * 128 + a_row] = av.x;
            As[(kk + 1) * 128 + a_row] = av.y;
            As[(kk + 2) * 128 + a_row] = av.z;
            As[(kk + 3) * 128 + a_row] = av.w;
        }
#pragma unroll
        for (int j = 0; j < 4; j++) {
            int f = j * 256 + tid;
            int kr = f >> 4, cc = (f & 15) * 4;
            *(float4*)&Vs[kr * VSTR2 + cc] =
                *(const float4*)(Bm + (size_t)(k0 + kr) * HD + cc);
        }
        __syncthreads();
#pragma unroll 8
        for (int k = 0; k < 64; k++) {
            float a[8], bb[4];
            *(float4*)(a)     = *(const float4*)&As[k * 128 + ty * 8];
            *(float4*)(a + 4) = *(const float4*)&As[k * 128 + ty * 8 + 4];
            *(float4*)(bb)    = *(const float4*)&Vs[k * VSTR2 + tx * 4];
#pragma unroll
            for (int i = 0; i < 8; i++)
#pragma unroll
                for (int j = 0; j < 4; j++)
                    acc[i][j] = fmaf(a[i], bb[j], acc[i][j]);
        }
    }

#pragma unroll
    for (int i = 0; i < 8; i++) {
        int m = m0 + ty * 8 + i;
        float4 w;
        w.x = acc[i][0]; w.y = acc[i][1]; w.z = acc[i][2]; w.w = acc[i][3];
        *(float4*)&ctx[((size_t)(b_ * SEQ + m)) * DM + h * HD + tx * 4] = w;
    }
}

__global__ void __launch_bounds__(256)
layernorm_rows(const float* __restrict__ pre, const float* __restrict__ g,
               const float* __restrict__ be, float* __restrict__ out)
{
    int warp = threadIdx.x >> 5, lane = threadIdx.x & 31;
    size_t row = (size_t)blockIdx.x * 8 + warp;
    const float* p = pre + row * DM;

    float x[16];
    float s = 0.f, s2 = 0.f;
#pragma unroll
    for (int i = 0; i < 4; i++) {
        float4 v = *(const float4*)(p + i * 128 + lane * 4);
        x[i * 4 + 0] = v.x; x[i * 4 + 1] = v.y;
        x[i * 4 + 2] = v.z; x[i * 4 + 3] = v.w;
        s  += v.x + v.y + v.z + v.w;
        s2 += v.x * v.x + v.y * v.y + v.z * v.z + v.w * v.w;
    }
#pragma unroll
    for (int o = 16; o; o >>= 1) {
        s  += __shfl_xor_sync(0xffffffffu, s,  o);
        s2 += __shfl_xor_sync(0xffffffffu, s2, o);
    }
    float mu  = s  * (1.f / DM);
    float var = s2 * (1.f / DM) - mu * mu;
    float inv = rsqrtf(var + 1e-6f);

    float* po = out + row * DM;
#pragma unroll
    for (int i = 0; i < 4; i++) {
        float4 w;
        int c = i * 128 + lane * 4;
        w.x = (x[i * 4 + 0] - mu) * inv * g[c + 0] + be[c + 0];
        w.y = (x[i * 4 + 1] - mu) * inv * g[c + 1] + be[c + 1];
        w.z = (x[i * 4 + 2] - mu) * inv * g[c + 2] + be[c + 2];
        w.w = (x[i * 4 + 3] - mu) * inv * g[c + 3] + be[c + 3];
        *(float4*)(po + c) = w;
    }
}

// ---------------------------------------------------------------------------
// Launch
// ---------------------------------------------------------------------------
extern "C" void kernel_launch(void* const* d_in, const int* in_sizes, int n_in,
                              void* d_out, int out_size)
{
    const float* Q   = (const float*)d_in[0];
    const float* K   = (const float*)d_in[1];
    const float* V   = (const float*)d_in[2];
    const int*   mask = (const int*)d_in[3];
    const float* adjoin = (const float*)d_in[4];
    const float* Wq = (const float*)d_in[5];
    const float* bq = (const float*)d_in[6];
    const float* Wk = (const float*)d_in[7];
    const float* bk = (const float*)d_in[8];
    const float* Wv = (const float*)d_in[9];
    const float* bv = (const float*)d_in[10];
    const float* Wo = (const float*)d_in[11];
    const float* bo = (const float*)d_in[12];
    const float* lg = (const float*)d_in[13];
    const float* lb = (const float*)d_in[14];

    float *qb, *kb, *vb, *cb, *pb, *afb;
    cudaGetSymbolAddress((void**)&qb,  g_q);
    cudaGetSymbolAddress((void**)&kb,  g_kT);
    cudaGetSymbolAddress((void**)&vb,  g_v);
    cudaGetSymbolAddress((void**)&cb,  g_ctx);
    cudaGetSymbolAddress((void**)&pb,  g_pre);
    cudaGetSymbolAddress((void**)&afb, g_attn_fb);

    float* out0 = (float*)d_out;
    const size_t OUT0 = (size_t)BSZ * SEQ * DM;
    const size_t ATTN = (size_t)BSZ * NH * SEQ * SEQ;
    float* attn = ((size_t)out_size >= OUT0 + ATTN) ? (out0 + OUT0) : afb;

    static int attr_set = 0;
    if (!attr_set) {
        cudaFuncSetAttribute(gemm_proj_mma<0>,
                             cudaFuncAttributeMaxDynamicSharedMemorySize, PROJ_SMEM);
        cudaFuncSetAttribute(gemm_proj_mma<1>,
                             cudaFuncAttributeMaxDynamicSharedMemorySize, PROJ_SMEM);
        cudaFuncSetAttribute(gemm_proj_mma<2>,
                             cudaFuncAttributeMaxDynamicSharedMemorySize, PROJ_SMEM);
        cudaFuncSetAttribute(gemm_scores2,
                             cudaFuncAttributeMaxDynamicSharedMemorySize, SC_SMEM);
        cudaFuncSetAttribute(gemm_ctx2,
                             cudaFuncAttributeMaxDynamicSharedMemorySize, CT_SMEM);
        attr_set = 1;
    }

    // 1) Projections on tensor cores (mma.sync bf16-split, fp32 accum)
    dim3 gp(DM / 128, (BSZ * SEQ) / 128);   // (4, 64)
    gemm_proj_mma<0><<<gp, 256, PROJ_SMEM>>>(Q, Wq, bq, nullptr, qb);
    gemm_proj_mma<1><<<gp, 256, PROJ_SMEM>>>(K, Wk, bk, nullptr, kb);
    gemm_proj_mma<0><<<gp, 256, PROJ_SMEM>>>(V, Wv, bv, nullptr, vb);

    // 2) Scores + scale + mask + adjoin
    dim3 gs(SEQ / 128, SEQ / 128, BSZ * NH);
    gemm_scores2<<<gs, 256, SC_SMEM>>>(qb, kb, mask, adjoin, attn);

    // 3) Softmax in place
    softmax_rows<<<(BSZ * NH * SEQ) / 8, 256>>>(attn);

    // 4) Context
    dim3 gc(1, SEQ / 128, BSZ * NH);
    gemm_ctx2<<<gc, 256, CT_SMEM>>>(attn, vb, cb);

    // 5) Output projection + bias + residual(Q) on tensor cores
    gemm_proj_mma<2><<<gp, 256, PROJ_SMEM>>>(cb, Wo, bo, Q, pb);

    // 6) LayerNorm -> out
    layernorm_rows<<<(BSZ * SEQ) / 8, 256>>>(pb, lg, lb, out0);
}

// round 7
// speedup vs baseline: 2.6358x; 1.3652x over previous
#include <cuda_runtime.h>
#include <cuda_bf16.h>
#include <math.h>
#include <stdint.h>

// Problem constants
#define BSZ 8
#define SEQ 1024
#define DM  512
#define NH  8
#define HD  64
#define NEGV (-1e9f)

// ---------------------------------------------------------------------------
// Scratch
// ---------------------------------------------------------------------------
__device__ float g_q  [(size_t)BSZ * NH * SEQ * HD];
__device__ float g_kT [(size_t)BSZ * NH * HD * SEQ];
__device__ float g_v  [(size_t)BSZ * NH * SEQ * HD];
__device__ float g_ctx[(size_t)BSZ * SEQ * DM];
__device__ float g_pre[(size_t)BSZ * SEQ * DM];
__device__ float g_attn_fb[(size_t)BSZ * NH * SEQ * SEQ];

// bf16-split operand buffers
__device__ __nv_bfloat16 g_xh[(size_t)BSZ * SEQ * DM];   // activation hi
__device__ __nv_bfloat16 g_xl[(size_t)BSZ * SEQ * DM];   // activation lo
__device__ __nv_bfloat16 g_wh[4][(size_t)DM * DM];       // W^T hi per matrix
__device__ __nv_bfloat16 g_wl[4][(size_t)DM * DM];       // W^T lo per matrix

// ===========================================================================
// mma.sync bf16 helper (verified mapping, R6)
// ===========================================================================
__device__ __forceinline__ void mma_bf16(float* d, const uint32_t* a,
                                         uint32_t b0, uint32_t b1)
{
    asm volatile(
        "mma.sync.aligned.m16n8k16.row.col.f32.bf16.bf16.f32 "
        "{%0,%1,%2,%3}, {%4,%5,%6,%7}, {%8,%9}, {%0,%1,%2,%3};"
        : "+f"(d[0]), "+f"(d[1]), "+f"(d[2]), "+f"(d[3])
        : "r"(a[0]), "r"(a[1]), "r"(a[2]), "r"(a[3]), "r"(b0), "r"(b1));
}

// ===========================================================================
// Pre-convert kernels
// ===========================================================================
// Activations: fp32 row-major -> hi/lo bf16 row-major
__global__ void __launch_bounds__(256)
convert_x(const float* __restrict__ A, __nv_bfloat16* __restrict__ hi,
          __nv_bfloat16* __restrict__ lo)
{
    size_t i = ((size_t)blockIdx.x * 256 + threadIdx.x) * 4;
    float4 v = *(const float4*)(A + i);
    __nv_bfloat16 h0 = __float2bfloat16(v.x), h1 = __float2bfloat16(v.y);
    __nv_bfloat16 h2 = __float2bfloat16(v.z), h3 = __float2bfloat16(v.w);
    __nv_bfloat162 ph0 = __halves2bfloat162(h0, h1);
    __nv_bfloat162 ph1 = __halves2bfloat162(h2, h3);
    __nv_bfloat162 pl0 = __halves2bfloat162(
        __float2bfloat16(v.x - __bfloat162float(h0)),
        __float2bfloat16(v.y - __bfloat162float(h1)));
    __nv_bfloat162 pl1 = __halves2bfloat162(
        __float2bfloat16(v.z - __bfloat162float(h2)),
        __float2bfloat16(v.w - __bfloat162float(h3)));
    uint2 uh = {*(uint32_t*)&ph0, *(uint32_t*)&ph1};
    uint2 ul = {*(uint32_t*)&pl0, *(uint32_t*)&pl1};
    *(uint2*)(hi + i) = uh;
    *(uint2*)(lo + i) = ul;
}

// Weights: W[k][n] fp32 -> Wt[n][k] hi/lo bf16 (smem transpose)
__global__ void __launch_bounds__(256)
convert_w(const float* __restrict__ W, __nv_bfloat16* __restrict__ th,
          __nv_bfloat16* __restrict__ tl)
{
    __shared__ float tile[32][33];
    int tx = threadIdx.x, ty = threadIdx.y;
    int n_in = blockIdx.x * 32 + tx;
    int k0 = blockIdx.y * 32;
#pragma unroll
    for (int j = ty; j < 32; j += 8)
        tile[j][tx] = W[(size_t)(k0 + j) * DM + n_in];
    __syncthreads();
#pragma unroll
    for (int j = ty; j < 32; j += 8) {
        int n = blockIdx.x * 32 + j;
        int k = k0 + tx;
        float v = tile[tx][j];
        __nv_bfloat16 h = __float2bfloat16(v);
        th[(size_t)n * DM + k] = h;
        tl[(size_t)n * DM + k] = __float2bfloat16(v - __bfloat162float(h));
    }
}

// ===========================================================================
// Tensor-core projection GEMM (pre-converted bf16 operands)
// acc += Ah*Bh + Ah*Bl + Al*Bh ; 128x128 tile, 8 warps 64x32, K-chunks of 64
// MODE 0: scatter [b,h,s,d]; MODE 1: scatter [b,h,d,s]; MODE 2: +resid row-major
// ===========================================================================
#define PSTR 72
#define PANEL (128 * PSTR)
#define PROJ_SMEM (4 * PANEL * 2)   // 73728 B

template<int MODE>
__global__ void __launch_bounds__(256)
gemm_proj_mma2(const __nv_bfloat16* __restrict__ Ahg,
               const __nv_bfloat16* __restrict__ Alg,
               const __nv_bfloat16* __restrict__ Bhg,
               const __nv_bfloat16* __restrict__ Blg,
               const float* __restrict__ bias, const float* __restrict__ resid,
               float* __restrict__ out)
{
    extern __shared__ __nv_bfloat16 sb[];
    __nv_bfloat16* Ah = sb;
    __nv_bfloat16* Al = Ah + PANEL;
    __nv_bfloat16* Bh = Al + PANEL;
    __nv_bfloat16* Bl = Bh + PANEL;

    const int tid = threadIdx.x, wid = tid >> 5, lane = tid & 31;
    const int m0 = blockIdx.y * 128, n0 = blockIdx.x * 128;
    const int wm = (wid >> 2) * 64;
    const int wn = (wid & 3) * 32;
    const int lg = lane >> 2;
    const int lq = lane & 3;

    float acc[4][4][4];
#pragma unroll
    for (int i = 0; i < 4; i++)
#pragma unroll
        for (int j = 0; j < 4; j++)
#pragma unroll
            for (int r = 0; r < 4; r++) acc[i][j][r] = 0.f;

    const int sr = tid >> 3;          // 0..31
    const int sc = (tid & 7) * 8;     // bf16 col within 64-k chunk

    for (int kc = 0; kc < 8; kc++) {
        const int k0 = kc * 64;
        __syncthreads();
#pragma unroll
        for (int p = 0; p < 4; p++) {
            int row = sr + p * 32;
            *(uint4*)&Ah[row * PSTR + sc] =
                *(const uint4*)(Ahg + (size_t)(m0 + row) * DM + k0 + sc);
            *(uint4*)&Al[row * PSTR + sc] =
                *(const uint4*)(Alg + (size_t)(m0 + row) * DM + k0 + sc);
            *(uint4*)&Bh[row * PSTR + sc] =
                *(const uint4*)(Bhg + (size_t)(n0 + row) * DM + k0 + sc);
            *(uint4*)&Bl[row * PSTR + sc] =
                *(const uint4*)(Blg + (size_t)(n0 + row) * DM + k0 + sc);
        }
        __syncthreads();

#pragma unroll
        for (int ks = 0; ks < 4; ks++) {
            const int kb = ks * 16;
            uint32_t ah[4][4], al[4][4];
#pragma unroll
            for (int i = 0; i < 4; i++) {
                int r = wm + i * 16 + lg;
                int c = kb + lq * 2;
                ah[i][0] = *(const uint32_t*)&Ah[r * PSTR + c];
                ah[i][1] = *(const uint32_t*)&Ah[(r + 8) * PSTR + c];
                ah[i][2] = *(const uint32_t*)&Ah[r * PSTR + c + 8];
                ah[i][3] = *(const uint32_t*)&Ah[(r + 8) * PSTR + c + 8];
                al[i][0] = *(const uint32_t*)&Al[r * PSTR + c];
                al[i][1] = *(const uint32_t*)&Al[(r + 8) * PSTR + c];
                al[i][2] = *(const uint32_t*)&Al[r * PSTR + c + 8];
                al[i][3] = *(const uint32_t*)&Al[(r + 8) * PSTR + c + 8];
            }
#pragma unroll
            for (int j = 0; j < 4; j++) {
                int n = wn + j * 8 + lg;
                int ck = kb + lq * 2;
                uint32_t bh0 = *(const uint32_t*)&Bh[n * PSTR + ck];
                uint32_t bh1 = *(const uint32_t*)&Bh[n * PSTR + ck + 8];
                uint32_t bl0 = *(const uint32_t*)&Bl[n * PSTR + ck];
                uint32_t bl1 = *(const uint32_t*)&Bl[n * PSTR + ck + 8];
#pragma unroll
                for (int i = 0; i < 4; i++) {
                    mma_bf16(acc[i][j], ah[i], bh0, bh1);
                    mma_bf16(acc[i][j], ah[i], bl0, bl1);
                    mma_bf16(acc[i][j], al[i], bh0, bh1);
                }
            }
        }
    }

#pragma unroll
    for (int i = 0; i < 4; i++) {
        int r1 = m0 + wm + i * 16 + lg;
        int r2 = r1 + 8;
#pragma unroll
        for (int j = 0; j < 4; j++) {
            int n = n0 + wn + j * 8 + lq * 2;
            float b0 = bias[n], b1 = bias[n + 1];
            float v00 = acc[i][j][0] + b0, v01 = acc[i][j][1] + b1;
            float v10 = acc[i][j][2] + b0, v11 = acc[i][j][3] + b1;
            if (MODE == 2) {
                float2 q1 = *(const float2*)(resid + (size_t)r1 * DM + n);
                float2 q2 = *(const float2*)(resid + (size_t)r2 * DM + n);
                float2 o1 = {v00 + q1.x, v01 + q1.y};
                float2 o2 = {v10 + q2.x, v11 + q2.y};
                *(float2*)(out + (size_t)r1 * DM + n) = o1;
                *(float2*)(out + (size_t)r2 * DM + n) = o2;
            } else if (MODE == 0) {
                int h = n >> 6, d = n & (HD - 1);
                int b1_ = r1 >> 10, s1 = r1 & (SEQ - 1);
                int b2_ = r2 >> 10, s2 = r2 & (SEQ - 1);
                float2 o1 = {v00, v01};
                float2 o2 = {v10, v11};
                *(float2*)(out + (((size_t)(b1_ * NH + h) * SEQ + s1) << 6) + d) = o1;
                *(float2*)(out + (((size_t)(b2_ * NH + h) * SEQ + s2) << 6) + d) = o2;
            } else {
                int h = n >> 6, d = n & (HD - 1);
                int b1_ = r1 >> 10, s1 = r1 & (SEQ - 1);
                int b2_ = r2 >> 10, s2 = r2 & (SEQ - 1);
                out[(((size_t)(b1_ * NH + h) * HD + d)     << 10) + s1] = v00;
                out[(((size_t)(b1_ * NH + h) * HD + d + 1) << 10) + s1] = v01;
                out[(((size_t)(b2_ * NH + h) * HD + d)     << 10) + s2] = v10;
                out[(((size_t)(b2_ * NH + h) * HD + d + 1) << 10) + s2] = v11;
            }
        }
    }
}

// ===========================================================================
// Attention path — identical to R4 (proven)
// ===========================================================================
#define SC_SMEM (2 * 64 * 128 * 4)
__global__ void __launch_bounds__(256)
gemm_scores2(const float* __restrict__ q, const float* __restrict__ kT,
             const int* __restrict__ mask,
             const float* __restrict__ adjoin,
             float* __restrict__ scores)
{
    extern __shared__ float sm[];
    float* As = sm;
    float* Bs = sm + 64 * 128;

    const int bh = blockIdx.z;
    const int b_ = bh >> 3;
    const float* A  = q  + (size_t)bh * SEQ * HD;
    const float* Bm = kT + (size_t)bh * HD * SEQ;
    float* out = scores + (size_t)bh * SEQ * SEQ;

    const int tid = threadIdx.x;
    const int tx = tid & 15, ty = tid >> 4;
    const int m0 = blockIdx.y * 128, n0 = blockIdx.x * 128;

    const int a_row = tid >> 1, a_col = (tid & 1) * 4;
    const int b_row = tid >> 5, b_col = (tid & 31) * 4;
#pragma unroll
    for (int j = 0; j < 8; j++) {
        int d0 = j * 8;
        float4 av = *(const float4*)(A + (size_t)(m0 + a_row) * HD + d0 + a_col);
        As[(d0 + a_col + 0) * 128 + a_row] = av.x;
        As[(d0 + a_col + 1) * 128 + a_row] = av.y;
        As[(d0 + a_col + 2) * 128 + a_row] = av.z;
        As[(d0 + a_col + 3) * 128 + a_row] = av.w;
        float4 bv = *(const float4*)(Bm + (size_t)(d0 + b_row) * SEQ + n0 + b_col);
        *(float4*)&Bs[(d0 + b_row) * 128 + b_col] = bv;
    }
    __syncthreads();

    float acc[8][8];
#pragma unroll
    for (int i = 0; i < 8; i++)
#pragma unroll
        for (int j = 0; j < 8; j++) acc[i][j] = 0.f;

#pragma unroll 8
    for (int d = 0; d < 64; d++) {
        float a[8], b[8];
        *(float4*)(a)     = *(const float4*)&As[d * 128 + ty * 8];
        *(float4*)(a + 4) = *(const float4*)&As[d * 128 + ty * 8 + 4];
        *(float4*)(b)     = *(const float4*)&Bs[d * 128 + tx * 8];
        *(float4*)(b + 4) = *(const float4*)&Bs[d * 128 + tx * 8 + 4];
#pragma unroll
        for (int i = 0; i < 8; i++)
#pragma unroll
            for (int j = 0; j < 8; j++)
                acc[i][j] = fmaf(a[i], b[j], acc[i][j]);
    }

    const int*   mb = mask   + (size_t)b_ * SEQ * SEQ;
    const float* ab = adjoin + (size_t)b_ * SEQ * SEQ;
#pragma unroll
    for (int i = 0; i < 8; i++) {
        int m = m0 + ty * 8 + i;
        size_t roff = (size_t)m * SEQ;
#pragma unroll
        for (int j = 0; j < 8; j += 4) {
            int n = n0 + tx * 8 + j;
            int4   m4 = *(const int4*)(mb + roff + n);
            float4 a4 = *(const float4*)(ab + roff + n);
            float4 s;
            s.x = (m4.x ? NEGV : acc[i][j + 0] * 0.125f) + a4.x;
            s.y = (m4.y ? NEGV : acc[i][j + 1] * 0.125f) + a4.y;
            s.z = (m4.z ? NEGV : acc[i][j + 2] * 0.125f) + a4.z;
            s.w = (m4.w ? NEGV : acc[i][j + 3] * 0.125f) + a4.w;
            *(float4*)(out + roff + n) = s;
        }
    }
}

__global__ void __launch_bounds__(256)
softmax_rows(float* __restrict__ scores)
{
    int warp = threadIdx.x >> 5, lane = threadIdx.x & 31;
    size_t row = (size_t)blockIdx.x * 8 + warp;
    float* p = scores + row * SEQ;

    float x[32];
    float mx = -INFINITY;
#pragma unroll
    for (int i = 0; i < 8; i++) {
        float4 v = *(const float4*)(p + i * 128 + lane * 4);
        x[i * 4 + 0] = v.x; x[i * 4 + 1] = v.y;
        x[i * 4 + 2] = v.z; x[i * 4 + 3] = v.w;
        mx = fmaxf(mx, fmaxf(fmaxf(v.x, v.y), fmaxf(v.z, v.w)));
    }
#pragma unroll
    for (int o = 16; o; o >>= 1) mx = fmaxf(mx, __shfl_xor_sync(0xffffffffu, mx, o));

    float sum = 0.f;
#pragma unroll
    for (int i = 0; i < 32; i++) { x[i] = __expf(x[i] - mx); sum += x[i]; }
#pragma unroll
    for (int o = 16; o; o >>= 1) sum += __shfl_xor_sync(0xffffffffu, sum, o);

    float inv = 1.f / sum;
#pragma unroll
    for (int i = 0; i < 8; i++) {
        float4 v;
        v.x = x[i * 4 + 0] * inv; v.y = x[i * 4 + 1] * inv;
        v.z = x[i * 4 + 2] * inv; v.w = x[i * 4 + 3] * inv;
        *(float4*)(p + i * 128 + lane * 4) = v;
    }
}

#define VSTR2 68
#define CT_SMEM ((64 * 128 + 64 * VSTR2) * 4)
__global__ void __launch_bounds__(256)
gemm_ctx2(const float* __restrict__ attn, const float* __restrict__ v,
          float* __restrict__ ctx)
{
    extern __shared__ float sm[];
    float* As = sm;
    float* Vs = sm + 64 * 128;

    const int bh = blockIdx.z;
    const int b_ = bh >> 3, h = bh & 7;
    const float* A  = attn + (size_t)bh * SEQ * SEQ;
    const float* Bm = v    + (size_t)bh * SEQ * HD;
    const int m0 = blockIdx.y * 128;

    const int tid = threadIdx.x;
    const int tx = tid & 15, ty = tid >> 4;

    float acc[8][4];
#pragma unroll
    for (int i = 0; i < 8; i++)
#pragma unroll
        for (int j = 0; j < 4; j++) acc[i][j] = 0.f;

    const int a_row = tid >> 1, a_col = (tid & 1) * 4;

    for (int k0 = 0; k0 < SEQ; k0 += 64) {
        __syncthreads();
#pragma unroll
        for (int j = 0; j < 8; j++) {
            int kk = j * 8 + a_col;
            float4 av = *(const float4*)(A + (size_t)(m0 + a_row) * SEQ + k0 + kk);
            As[(kk + 0) * 128 + a_row] = av.x;
            As[(kk + 1) * 128 + a_row] = av.y;
            As[(kk + 2) * 128 + a_row] = av.z;
            As[(kk + 3) * 128 + a_row] = av.w;
        }
#pragma unroll
        for (int j = 0; j < 4; j++) {
            int f = j * 256 + tid;
            int kr = f >> 4, cc = (f & 15) * 4;
            *(float4*)&Vs[kr * VSTR2 + cc] =
                *(const float4*)(Bm + (size_t)(k0 + kr) * HD + cc);
        }
        __syncthreads();
#pragma unroll 8
        for (int k = 0; k < 64; k++) {
            float a[8], bb[4];
            *(float4*)(a)     = *(const float4*)&As[k * 128 + ty * 8];
            *(float4*)(a + 4) = *(const float4*)&As[k * 128 + ty * 8 + 4];
            *(float4*)(bb)    = *(const float4*)&Vs[k * VSTR2 + tx * 4];
#pragma unroll
            for (int i = 0; i < 8; i++)
#pragma unroll
                for (int j = 0; j < 4; j++)
                    acc[i][j] = fmaf(a[i], bb[j], acc[i][j]);
        }
    }

#pragma unroll
    for (int i = 0; i < 8; i++) {
        int m = m0 + ty * 8 + i;
        float4 w;
        w.x = acc[i][0]; w.y = acc[i][1]; w.z = acc[i][2]; w.w = acc[i][3];
        *(float4*)&ctx[((size_t)(b_ * SEQ + m)) * DM + h * HD + tx * 4] = w;
    }
}

__global__ void __launch_bounds__(256)
layernorm_rows(const float* __restrict__ pre, const float* __restrict__ g,
               const float* __restrict__ be, float* __restrict__ out)
{
    int warp = threadIdx.x >> 5, lane = threadIdx.x & 31;
    size_t row = (size_t)blockIdx.x * 8 + warp;
    const float* p = pre + row * DM;

    float x[16];
    float s = 0.f, s2 = 0.f;
#pragma unroll
    for (int i = 0; i < 4; i++) {
        float4 v = *(const float4*)(p + i * 128 + lane * 4);
        x[i * 4 + 0] = v.x; x[i * 4 + 1] = v.y;
        x[i * 4 + 2] = v.z; x[i * 4 + 3] = v.w;
        s  += v.x + v.y + v.z + v.w;
        s2 += v.x * v.x + v.y * v.y + v.z * v.z + v.w * v.w;
    }
#pragma unroll
    for (int o = 16; o; o >>= 1) {
        s  += __shfl_xor_sync(0xffffffffu, s,  o);
        s2 += __shfl_xor_sync(0xffffffffu, s2, o);
    }
    float mu  = s  * (1.f / DM);
    float var = s2 * (1.f / DM) - mu * mu;
    float inv = rsqrtf(var + 1e-6f);

    float* po = out + row * DM;
#pragma unroll
    for (int i = 0; i < 4; i++) {
        float4 w;
        int c = i * 128 + lane * 4;
        w.x = (x[i * 4 + 0] - mu) * inv * g[c + 0] + be[c + 0];
        w.y = (x[i * 4 + 1] - mu) * inv * g[c + 1] + be[c + 1];
        w.z = (x[i * 4 + 2] - mu) * inv * g[c + 2] + be[c + 2];
        w.w = (x[i * 4 + 3] - mu) * inv * g[c + 3] + be[c + 3];
        *(float4*)(po + c) = w;
    }
}

// ---------------------------------------------------------------------------
// Launch
// ---------------------------------------------------------------------------
extern "C" void kernel_launch(void* const* d_in, const int* in_sizes, int n_in,
                              void* d_out, int out_size)
{
    const float* Q   = (const float*)d_in[0];
    const float* K   = (const float*)d_in[1];
    const float* V   = (const float*)d_in[2];
    const int*   mask = (const int*)d_in[3];
    const float* adjoin = (const float*)d_in[4];
    const float* Wq = (const float*)d_in[5];
    const float* bq = (const float*)d_in[6];
    const float* Wk = (const float*)d_in[7];
    const float* bk = (const float*)d_in[8];
    const float* Wv = (const float*)d_in[9];
    const float* bv = (const float*)d_in[10];
    const float* Wo = (const float*)d_in[11];
    const float* bo = (const float*)d_in[12];
    const float* lg = (const float*)d_in[13];
    const float* lb = (const float*)d_in[14];

    float *qb, *kb, *vb, *cb, *pb, *afb;
    cudaGetSymbolAddress((void**)&qb,  g_q);
    cudaGetSymbolAddress((void**)&kb,  g_kT);
    cudaGetSymbolAddress((void**)&vb,  g_v);
    cudaGetSymbolAddress((void**)&cb,  g_ctx);
    cudaGetSymbolAddress((void**)&pb,  g_pre);
    cudaGetSymbolAddress((void**)&afb, g_attn_fb);

    __nv_bfloat16 *xh, *xl, *wh, *wl;
    cudaGetSymbolAddress((void**)&xh, g_xh);
    cudaGetSymbolAddress((void**)&xl, g_xl);
    cudaGetSymbolAddress((void**)&wh, g_wh);
    cudaGetSymbolAddress((void**)&wl, g_wl);
    const size_t WSZ = (size_t)DM * DM;

    float* out0 = (float*)d_out;
    const size_t OUT0 = (size_t)BSZ * SEQ * DM;
    const size_t ATTN = (size_t)BSZ * NH * SEQ * SEQ;
    float* attn = ((size_t)out_size >= OUT0 + ATTN) ? (out0 + OUT0) : afb;

    static int attr_set = 0;
    if (!attr_set) {
        cudaFuncSetAttribute(gemm_proj_mma2<0>,
                             cudaFuncAttributeMaxDynamicSharedMemorySize, PROJ_SMEM);
        cudaFuncSetAttribute(gemm_proj_mma2<1>,
                             cudaFuncAttributeMaxDynamicSharedMemorySize, PROJ_SMEM);
        cudaFuncSetAttribute(gemm_proj_mma2<2>,
                             cudaFuncAttributeMaxDynamicSharedMemorySize, PROJ_SMEM);
        cudaFuncSetAttribute(gemm_scores2,
                             cudaFuncAttributeMaxDynamicSharedMemorySize, SC_SMEM);
        cudaFuncSetAttribute(gemm_ctx2,
                             cudaFuncAttributeMaxDynamicSharedMemorySize, CT_SMEM);
        attr_set = 1;
    }

    dim3 wgrid(DM / 32, DM / 32), wblk(32, 8);
    const int XBLK = (int)(((size_t)BSZ * SEQ * DM) / 4 / 256);   // 4096
    dim3 gp(DM / 128, (BSZ * SEQ) / 128);   // (4, 64)

    // 0) Pre-convert weights (hi/lo, transposed to [n][k])
    convert_w<<<wgrid, wblk>>>(Wq, wh + 0 * WSZ, wl + 0 * WSZ);
    convert_w<<<wgrid, wblk>>>(Wk, wh + 1 * WSZ, wl + 1 * WSZ);
    convert_w<<<wgrid, wblk>>>(Wv, wh + 2 * WSZ, wl + 2 * WSZ);
    convert_w<<<wgrid, wblk>>>(Wo, wh + 3 * WSZ, wl + 3 * WSZ);

    // 1) Projections: convert activation, then MMA GEMM (x-buffer reused)
    convert_x<<<XBLK, 256>>>(Q, xh, xl);
    gemm_proj_mma2<0><<<gp, 256, PROJ_SMEM>>>(xh, xl, wh + 0 * WSZ, wl + 0 * WSZ,
                                              bq, nullptr, qb);
    convert_x<<<XBLK, 256>>>(K, xh, xl);
    gemm_proj_mma2<1><<<gp, 256, PROJ_SMEM>>>(xh, xl, wh + 1 * WSZ, wl + 1 * WSZ,
                                              bk, nullptr, kb);
    convert_x<<<XBLK, 256>>>(V, xh, xl);
    gemm_proj_mma2<0><<<gp, 256, PROJ_SMEM>>>(xh, xl, wh + 2 * WSZ, wl + 2 * WSZ,
                                              bv, nullptr, vb);

    // 2) Scores + scale + mask + adjoin
    dim3 gs(SEQ / 128, SEQ / 128, BSZ * NH);
    gemm_scores2<<<gs, 256, SC_SMEM>>>(qb, kb, mask, adjoin, attn);

    // 3) Softmax in place
    softmax_rows<<<(BSZ * NH * SEQ) / 8, 256>>>(attn);

    // 4) Context
    dim3 gc(1, SEQ / 128, BSZ * NH);
    gemm_ctx2<<<gc, 256, CT_SMEM>>>(attn, vb, cb);

    // 5) Output projection + bias + residual(Q)
    convert_x<<<XBLK, 256>>>(cb, xh, xl);
    gemm_proj_mma2<2><<<gp, 256, PROJ_SMEM>>>(xh, xl, wh + 3 * WSZ, wl + 3 * WSZ,
                                              bo, Q, pb);

    // 6) LayerNorm -> out
    layernorm_rows<<<(BSZ * SEQ) / 8, 256>>>(pb, lg, lb, out0);
}

// round 8
// speedup vs baseline: 3.4323x; 1.3022x over previous
#include <cuda_runtime.h>
#include <cuda_bf16.h>
#include <math.h>
#include <stdint.h>

// Problem constants
#define BSZ 8
#define SEQ 1024
#define DM  512
#define NH  8
#define HD  64
#define NEGV (-1e9f)

// ---------------------------------------------------------------------------
// Scratch
// ---------------------------------------------------------------------------
__device__ float g_ctx[(size_t)BSZ * SEQ * DM];
__device__ float g_pre[(size_t)BSZ * SEQ * DM];
__device__ float g_attn_fb[(size_t)BSZ * NH * SEQ * SEQ];

__device__ __nv_bfloat16 g_xh[(size_t)BSZ * SEQ * DM];   // activation hi
__device__ __nv_bfloat16 g_xl[(size_t)BSZ * SEQ * DM];   // activation lo
__device__ __nv_bfloat16 g_wh[4][(size_t)DM * DM];       // W^T hi
__device__ __nv_bfloat16 g_wl[4][(size_t)DM * DM];       // W^T lo

__device__ __nv_bfloat16 g_qh[(size_t)BSZ * NH * SEQ * HD];  // q hi [b,h,s,d]
__device__ __nv_bfloat16 g_ql[(size_t)BSZ * NH * SEQ * HD];
__device__ __nv_bfloat16 g_kh[(size_t)BSZ * NH * SEQ * HD];  // k hi [b,h,s,d]
__device__ __nv_bfloat16 g_kl[(size_t)BSZ * NH * SEQ * HD];
__device__ __nv_bfloat16 g_vh[(size_t)BSZ * NH * HD * SEQ];  // v hi [b,h,d,s]
__device__ __nv_bfloat16 g_vl[(size_t)BSZ * NH * HD * SEQ];
__device__ __nv_bfloat16 g_ph[(size_t)BSZ * NH * SEQ * SEQ]; // P bf16

// ===========================================================================
// mma.sync bf16 helper (verified mapping)
// ===========================================================================
__device__ __forceinline__ void mma_bf16(float* d, const uint32_t* a,
                                         uint32_t b0, uint32_t b1)
{
    asm volatile(
        "mma.sync.aligned.m16n8k16.row.col.f32.bf16.bf16.f32 "
        "{%0,%1,%2,%3}, {%4,%5,%6,%7}, {%8,%9}, {%0,%1,%2,%3};"
        : "+f"(d[0]), "+f"(d[1]), "+f"(d[2]), "+f"(d[3])
        : "r"(a[0]), "r"(a[1]), "r"(a[2]), "r"(a[3]), "r"(b0), "r"(b1));
}

__device__ __forceinline__ uint32_t packh2(float x, float y) {
    __nv_bfloat162 p = __halves2bfloat162(__float2bfloat16(x), __float2bfloat16(y));
    return *(uint32_t*)&p;
}
__device__ __forceinline__ uint32_t packl2(float x, float y) {
    __nv_bfloat16 hx = __float2bfloat16(x), hy = __float2bfloat16(y);
    __nv_bfloat162 p = __halves2bfloat162(
        __float2bfloat16(x - __bfloat162float(hx)),
        __float2bfloat16(y - __bfloat162float(hy)));
    return *(uint32_t*)&p;
}

// ===========================================================================
// Pre-convert kernels (proven R7)
// ===========================================================================
__global__ void __launch_bounds__(256)
convert_x(const float* __restrict__ A, __nv_bfloat16* __restrict__ hi,
          __nv_bfloat16* __restrict__ lo)
{
    size_t i = ((size_t)blockIdx.x * 256 + threadIdx.x) * 4;
    float4 v = *(const float4*)(A + i);
    uint2 uh = {packh2(v.x, v.y), packh2(v.z, v.w)};
    uint2 ul = {packl2(v.x, v.y), packl2(v.z, v.w)};
    *(uint2*)(hi + i) = uh;
    *(uint2*)(lo + i) = ul;
}

__global__ void __launch_bounds__(256)
convert_w(const float* __restrict__ W, __nv_bfloat16* __restrict__ th,
          __nv_bfloat16* __restrict__ tl)
{
    __shared__ float tile[32][33];
    int tx = threadIdx.x, ty = threadIdx.y;
    int n_in = blockIdx.x * 32 + tx;
    int k0 = blockIdx.y * 32;
#pragma unroll
    for (int j = ty; j < 32; j += 8)
        tile[j][tx] = W[(size_t)(k0 + j) * DM + n_in];
    __syncthreads();
#pragma unroll
    for (int j = ty; j < 32; j += 8) {
        int n = blockIdx.x * 32 + j;
        int k = k0 + tx;
        float v = tile[tx][j];
        __nv_bfloat16 h = __float2bfloat16(v);
        th[(size_t)n * DM + k] = h;
        tl[(size_t)n * DM + k] = __float2bfloat16(v - __bfloat162float(h));
    }
}

// ===========================================================================
// Projection GEMM via mma.sync (pre-converted operands)
// MODE 0: bf16 hi/lo out [b,h,s,d]   (q / k)
// MODE 1: bf16 hi/lo out [b,h,d,s]   (v)
// MODE 2: fp32 + resid row-major     (output proj)
// ===========================================================================
#define PSTR 72
#define PANEL (128 * PSTR)
#define PROJ_SMEM (4 * PANEL * 2)   // 73728 B

template<int MODE>
__global__ void __launch_bounds__(256)
gemm_proj_mma3(const __nv_bfloat16* __restrict__ Ahg,
               const __nv_bfloat16* __restrict__ Alg,
               const __nv_bfloat16* __restrict__ Bhg,
               const __nv_bfloat16* __restrict__ Blg,
               const float* __restrict__ bias, const float* __restrict__ resid,
               float* __restrict__ outf,
               __nv_bfloat16* __restrict__ outh, __nv_bfloat16* __restrict__ outl)
{
    extern __shared__ __nv_bfloat16 sb[];
    __nv_bfloat16* Ah = sb;
    __nv_bfloat16* Al = Ah + PANEL;
    __nv_bfloat16* Bh = Al + PANEL;
    __nv_bfloat16* Bl = Bh + PANEL;

    const int tid = threadIdx.x, wid = tid >> 5, lane = tid & 31;
    const int m0 = blockIdx.y * 128, n0 = blockIdx.x * 128;
    const int wm = (wid >> 2) * 64;
    const int wn = (wid & 3) * 32;
    const int lg = lane >> 2;
    const int lq = lane & 3;

    float acc[4][4][4];
#pragma unroll
    for (int i = 0; i < 4; i++)
#pragma unroll
        for (int j = 0; j < 4; j++)
#pragma unroll
            for (int r = 0; r < 4; r++) acc[i][j][r] = 0.f;

    const int sr = tid >> 3;
    const int sc = (tid & 7) * 8;

    for (int kc = 0; kc < 8; kc++) {
        const int k0 = kc * 64;
        __syncthreads();
#pragma unroll
        for (int p = 0; p < 4; p++) {
            int row = sr + p * 32;
            *(uint4*)&Ah[row * PSTR + sc] =
                *(const uint4*)(Ahg + (size_t)(m0 + row) * DM + k0 + sc);
            *(uint4*)&Al[row * PSTR + sc] =
                *(const uint4*)(Alg + (size_t)(m0 + row) * DM + k0 + sc);
            *(uint4*)&Bh[row * PSTR + sc] =
                *(const uint4*)(Bhg + (size_t)(n0 + row) * DM + k0 + sc);
            *(uint4*)&Bl[row * PSTR + sc] =
                *(const uint4*)(Blg + (size_t)(n0 + row) * DM + k0 + sc);
        }
        __syncthreads();

#pragma unroll
        for (int ks = 0; ks < 4; ks++) {
            const int kb = ks * 16;
            uint32_t ah[4][4], al[4][4];
#pragma unroll
            for (int i = 0; i < 4; i++) {
                int r = wm + i * 16 + lg;
                int c = kb + lq * 2;
                ah[i][0] = *(const uint32_t*)&Ah[r * PSTR + c];
                ah[i][1] = *(const uint32_t*)&Ah[(r + 8) * PSTR + c];
                ah[i][2] = *(const uint32_t*)&Ah[r * PSTR + c + 8];
                ah[i][3] = *(const uint32_t*)&Ah[(r + 8) * PSTR + c + 8];
                al[i][0] = *(const uint32_t*)&Al[r * PSTR + c];
                al[i][1] = *(const uint32_t*)&Al[(r + 8) * PSTR + c];
                al[i][2] = *(const uint32_t*)&Al[r * PSTR + c + 8];
                al[i][3] = *(const uint32_t*)&Al[(r + 8) * PSTR + c + 8];
            }
#pragma unroll
            for (int j = 0; j < 4; j++) {
                int n = wn + j * 8 + lg;
                int ck = kb + lq * 2;
                uint32_t bh0 = *(const uint32_t*)&Bh[n * PSTR + ck];
                uint32_t bh1 = *(const uint32_t*)&Bh[n * PSTR + ck + 8];
                uint32_t bl0 = *(const uint32_t*)&Bl[n * PSTR + ck];
                uint32_t bl1 = *(const uint32_t*)&Bl[n * PSTR + ck + 8];
#pragma unroll
                for (int i = 0; i < 4; i++) {
                    mma_bf16(acc[i][j], ah[i], bh0, bh1);
                    mma_bf16(acc[i][j], ah[i], bl0, bl1);
                    mma_bf16(acc[i][j], al[i], bh0, bh1);
                }
            }
        }
    }

#pragma unroll
    for (int i = 0; i < 4; i++) {
        int r1 = m0 + wm + i * 16 + lg;
        int r2 = r1 + 8;
#pragma unroll
        for (int j = 0; j < 4; j++) {
            int n = n0 + wn + j * 8 + lq * 2;
            float b0 = bias[n], b1 = bias[n + 1];
            float v00 = acc[i][j][0] + b0, v01 = acc[i][j][1] + b1;
            float v10 = acc[i][j][2] + b0, v11 = acc[i][j][3] + b1;
            if (MODE == 2) {
                float2 q1 = *(const float2*)(resid + (size_t)r1 * DM + n);
                float2 q2 = *(const float2*)(resid + (size_t)r2 * DM + n);
                float2 o1 = {v00 + q1.x, v01 + q1.y};
                float2 o2 = {v10 + q2.x, v11 + q2.y};
                *(float2*)(outf + (size_t)r1 * DM + n) = o1;
                *(float2*)(outf + (size_t)r2 * DM + n) = o2;
            } else if (MODE == 0) {
                int h = n >> 6, d = n & (HD - 1);
                int b1_ = r1 >> 10, s1 = r1 & (SEQ - 1);
                int b2_ = r2 >> 10, s2 = r2 & (SEQ - 1);
                size_t o1 = (((size_t)(b1_ * NH + h) * SEQ + s1) << 6) + d;
                size_t o2 = (((size_t)(b2_ * NH + h) * SEQ + s2) << 6) + d;
                *(uint32_t*)(outh + o1) = packh2(v00, v01);
                *(uint32_t*)(outl + o1) = packl2(v00, v01);
                *(uint32_t*)(outh + o2) = packh2(v10, v11);
                *(uint32_t*)(outl + o2) = packl2(v10, v11);
            } else {
                int h = n >> 6, d = n & (HD - 1);
                int b1_ = r1 >> 10, s1 = r1 & (SEQ - 1);
                int b2_ = r2 >> 10, s2 = r2 & (SEQ - 1);
                size_t base1 = (((size_t)(b1_ * NH + h) * HD + d) << 10) + s1;
                size_t base2 = (((size_t)(b2_ * NH + h) * HD + d) << 10) + s2;
                __nv_bfloat16 h00 = __float2bfloat16(v00);
                __nv_bfloat16 h01 = __float2bfloat16(v01);
                __nv_bfloat16 h10 = __float2bfloat16(v10);
                __nv_bfloat16 h11 = __float2bfloat16(v11);
                outh[base1]          = h00;
                outh[base1 + SEQ]    = h01;
                outh[base2]          = h10;
                outh[base2 + SEQ]    = h11;
                outl[base1]       = __float2bfloat16(v00 - __bfloat162float(h00));
                outl[base1 + SEQ] = __float2bfloat16(v01 - __bfloat162float(h01));
                outl[base2]       = __float2bfloat16(v10 - __bfloat162float(h10));
                outl[base2 + SEQ] = __float2bfloat16(v11 - __bfloat162float(h11));
            }
        }
    }
}

// ===========================================================================
// Scores via mma.sync: S = q @ k^T /8, mask, +adjoin. K=64 single chunk.
// 3-pass bf16 split. grid (8,8,64), 256 thr.
// ===========================================================================
#define SCM_SMEM (4 * PANEL * 2)
__global__ void __launch_bounds__(256)
gemm_scores_mma(const __nv_bfloat16* __restrict__ qh, const __nv_bfloat16* __restrict__ ql,
                const __nv_bfloat16* __restrict__ kh, const __nv_bfloat16* __restrict__ kl,
                const int* __restrict__ mask, const float* __restrict__ adjoin,
                float* __restrict__ scores)
{
    extern __shared__ __nv_bfloat16 sb[];
    __nv_bfloat16* Qh = sb;
    __nv_bfloat16* Ql = Qh + PANEL;
    __nv_bfloat16* Kh = Ql + PANEL;
    __nv_bfloat16* Kl = Kh + PANEL;

    const int bh = blockIdx.z;
    const int b_ = bh >> 3;
    const __nv_bfloat16* qg_h = qh + (size_t)bh * SEQ * HD;
    const __nv_bfloat16* qg_l = ql + (size_t)bh * SEQ * HD;
    const __nv_bfloat16* kg_h = kh + (size_t)bh * SEQ * HD;
    const __nv_bfloat16* kg_l = kl + (size_t)bh * SEQ * HD;
    float* out = scores + (size_t)bh * SEQ * SEQ;

    const int tid = threadIdx.x, wid = tid >> 5, lane = tid & 31;
    const int m0 = blockIdx.y * 128, n0 = blockIdx.x * 128;
    const int wm = (wid >> 2) * 64;
    const int wn = (wid & 3) * 32;
    const int lg = lane >> 2;
    const int lq = lane & 3;

    const int sr = tid >> 3;
    const int sc = (tid & 7) * 8;
#pragma unroll
    for (int p = 0; p < 4; p++) {
        int row = sr + p * 32;
        *(uint4*)&Qh[row * PSTR + sc] = *(const uint4*)(qg_h + (size_t)(m0 + row) * HD + sc);
        *(uint4*)&Ql[row * PSTR + sc] = *(const uint4*)(qg_l + (size_t)(m0 + row) * HD + sc);
        *(uint4*)&Kh[row * PSTR + sc] = *(const uint4*)(kg_h + (size_t)(n0 + row) * HD + sc);
        *(uint4*)&Kl[row * PSTR + sc] = *(const uint4*)(kg_l + (size_t)(n0 + row) * HD + sc);
    }
    __syncthreads();

    float acc[4][4][4];
#pragma unroll
    for (int i = 0; i < 4; i++)
#pragma unroll
        for (int j = 0; j < 4; j++)
#pragma unroll
            for (int r = 0; r < 4; r++) acc[i][j][r] = 0.f;

#pragma unroll
    for (int ks = 0; ks < 4; ks++) {
        const int kb = ks * 16;
        uint32_t ah[4][4], al[4][4];
#pragma unroll
        for (int i = 0; i < 4; i++) {
            int r = wm + i * 16 + lg;
            int c = kb + lq * 2;
            ah[i][0] = *(const uint32_t*)&Qh[r * PSTR + c];
            ah[i][1] = *(const uint32_t*)&Qh[(r + 8) * PSTR + c];
            ah[i][2] = *(const uint32_t*)&Qh[r * PSTR + c + 8];
            ah[i][3] = *(const uint32_t*)&Qh[(r + 8) * PSTR + c + 8];
            al[i][0] = *(const uint32_t*)&Ql[r * PSTR + c];
            al[i][1] = *(const uint32_t*)&Ql[(r + 8) * PSTR + c];
            al[i][2] = *(const uint32_t*)&Ql[r * PSTR + c + 8];
            al[i][3] = *(const uint32_t*)&Ql[(r + 8) * PSTR + c + 8];
        }
#pragma unroll
        for (int j = 0; j < 4; j++) {
            int n = wn + j * 8 + lg;
            int ck = kb + lq * 2;
            uint32_t bh0 = *(const uint32_t*)&Kh[n * PSTR + ck];
            uint32_t bh1 = *(const uint32_t*)&Kh[n * PSTR + ck + 8];
            uint32_t bl0 = *(const uint32_t*)&Kl[n * PSTR + ck];
            uint32_t bl1 = *(const uint32_t*)&Kl[n * PSTR + ck + 8];
#pragma unroll
            for (int i = 0; i < 4; i++) {
                mma_bf16(acc[i][j], ah[i], bh0, bh1);
                mma_bf16(acc[i][j], ah[i], bl0, bl1);
                mma_bf16(acc[i][j], al[i], bh0, bh1);
            }
        }
    }

    const int*   mb = mask   + (size_t)b_ * SEQ * SEQ;
    const float* ab = adjoin + (size_t)b_ * SEQ * SEQ;
#pragma unroll
    for (int i = 0; i < 4; i++) {
        int r1 = m0 + wm + i * 16 + lg;
        int r2 = r1 + 8;
#pragma unroll
        for (int j = 0; j < 4; j++) {
            int n = n0 + wn + j * 8 + lq * 2;
            size_t o1 = (size_t)r1 * SEQ + n;
            size_t o2 = (size_t)r2 * SEQ + n;
            int2   m1 = *(const int2*)(mb + o1);
            int2   m2 = *(const int2*)(mb + o2);
            float2 a1 = *(const float2*)(ab + o1);
            float2 a2 = *(const float2*)(ab + o2);
            float2 s1, s2;
            s1.x = (m1.x ? NEGV : acc[i][j][0] * 0.125f) + a1.x;
            s1.y = (m1.y ? NEGV : acc[i][j][1] * 0.125f) + a1.y;
            s2.x = (m2.x ? NEGV : acc[i][j][2] * 0.125f) + a2.x;
            s2.y = (m2.y ? NEGV : acc[i][j][3] * 0.125f) + a2.y;
            *(float2*)(out + o1) = s1;
            *(float2*)(out + o2) = s2;
        }
    }
}

// ===========================================================================
// Softmax: fp32 in place + bf16 P out
// ===========================================================================
__global__ void __launch_bounds__(256)
softmax_rows(float* __restrict__ scores, __nv_bfloat16* __restrict__ ph)
{
    int warp = threadIdx.x >> 5, lane = threadIdx.x & 31;
    size_t row = (size_t)blockIdx.x * 8 + warp;
    float* p = scores + row * SEQ;
    __nv_bfloat16* pb = ph + row * SEQ;

    float x[32];
    float mx = -INFINITY;
#pragma unroll
    for (int i = 0; i < 8; i++) {
        float4 v = *(const float4*)(p + i * 128 + lane * 4);
        x[i * 4 + 0] = v.x; x[i * 4 + 1] = v.y;
        x[i * 4 + 2] = v.z; x[i * 4 + 3] = v.w;
        mx = fmaxf(mx, fmaxf(fmaxf(v.x, v.y), fmaxf(v.z, v.w)));
    }
#pragma unroll
    for (int o = 16; o; o >>= 1) mx = fmaxf(mx, __shfl_xor_sync(0xffffffffu, mx, o));

    float sum = 0.f;
#pragma unroll
    for (int i = 0; i < 32; i++) { x[i] = __expf(x[i] - mx); sum += x[i]; }
#pragma unroll
    for (int o = 16; o; o >>= 1) sum += __shfl_xor_sync(0xffffffffu, sum, o);

    float inv = 1.f / sum;
#pragma unroll
    for (int i = 0; i < 8; i++) {
        float4 v;
        v.x = x[i * 4 + 0] * inv; v.y = x[i * 4 + 1] * inv;
        v.z = x[i * 4 + 2] * inv; v.w = x[i * 4 + 3] * inv;
        *(float4*)(p + i * 128 + lane * 4) = v;
        uint2 u = {packh2(v.x, v.y), packh2(v.z, v.w)};
        *(uint2*)(pb + i * 128 + lane * 4) = u;
    }
}

// ===========================================================================
// Ctx via mma.sync: ctx = P(bf16) @ V(bf16 hi/lo), 2 passes.
// grid (8 mtiles, 64 bh), 256 thr. smem static 36.9KB.
// ===========================================================================
__global__ void __launch_bounds__(256)
gemm_ctx_mma(const __nv_bfloat16* __restrict__ ph,
             const __nv_bfloat16* __restrict__ vh, const __nv_bfloat16* __restrict__ vl,
             float* __restrict__ ctx)
{
    __shared__ __nv_bfloat16 Ps[128 * PSTR];
    __shared__ __nv_bfloat16 Vh[64 * PSTR];
    __shared__ __nv_bfloat16 Vl[64 * PSTR];

    const int bh = blockIdx.y;
    const int b_ = bh >> 3, h = bh & 7;
    const int m0 = blockIdx.x * 128;
    const __nv_bfloat16* pg = ph + (size_t)bh * SEQ * SEQ;
    const __nv_bfloat16* vg_h = vh + (size_t)bh * HD * SEQ;
    const __nv_bfloat16* vg_l = vl + (size_t)bh * HD * SEQ;

    const int tid = threadIdx.x, wid = tid >> 5, lane = tid & 31;
    const int wm = (wid >> 1) * 32;
    const int wn = (wid & 1) * 32;
    const int lg = lane >> 2;
    const int lq = lane & 3;

    float acc[2][4][4];
#pragma unroll
    for (int i = 0; i < 2; i++)
#pragma unroll
        for (int j = 0; j < 4; j++)
#pragma unroll
            for (int r = 0; r < 4; r++) acc[i][j][r] = 0.f;

    for (int k0 = 0; k0 < SEQ; k0 += 64) {
        __syncthreads();
#pragma unroll
        for (int p = 0; p < 4; p++) {
            int f = p * 256 + tid;
            int row = f >> 3, col = (f & 7) * 8;
            *(uint4*)&Ps[row * PSTR + col] =
                *(const uint4*)(pg + (size_t)(m0 + row) * SEQ + k0 + col);
        }
#pragma unroll
        for (int p = 0; p < 2; p++) {
            int f = p * 256 + tid;
            int row = f >> 3, col = (f & 7) * 8;
            *(uint4*)&Vh[row * PSTR + col] =
                *(const uint4*)(vg_h + ((size_t)row << 10) + k0 + col);
            *(uint4*)&Vl[row * PSTR + col] =
                *(const uint4*)(vg_l + ((size_t)row << 10) + k0 + col);
        }
        __syncthreads();

#pragma unroll
        for (int ks = 0; ks < 4; ks++) {
            const int kb = ks * 16;
            uint32_t a[2][4];
#pragma unroll
            for (int i = 0; i < 2; i++) {
                int r = wm + i * 16 + lg;
                int c = kb + lq * 2;
                a[i][0] = *(const uint32_t*)&Ps[r * PSTR + c];
                a[i][1] = *(const uint32_t*)&Ps[(r + 8) * PSTR + c];
                a[i][2] = *(const uint32_t*)&Ps[r * PSTR + c + 8];
                a[i][3] = *(const uint32_t*)&Ps[(r + 8) * PSTR + c + 8];
            }
#pragma unroll
            for (int j = 0; j < 4; j++) {
                int n = wn + j * 8 + lg;
                int ck = kb + lq * 2;
                uint32_t bh0 = *(const uint32_t*)&Vh[n * PSTR + ck];
                uint32_t bh1 = *(const uint32_t*)&Vh[n * PSTR + ck + 8];
                uint32_t bl0 = *(const uint32_t*)&Vl[n * PSTR + ck];
                uint32_t bl1 = *(const uint32_t*)&Vl[n * PSTR + ck + 8];
#pragma unroll
                for (int i = 0; i < 2; i++) {
                    mma_bf16(acc[i][j], a[i], bh0, bh1);
                    mma_bf16(acc[i][j], a[i], bl0, bl1);
                }
            }
        }
    }

#pragma unroll
    for (int i = 0; i < 2; i++) {
        int r1 = m0 + wm + i * 16 + lg;
        int r2 = r1 + 8;
#pragma unroll
        for (int j = 0; j < 4; j++) {
            int d = wn + j * 8 + lq * 2;
            float2 o1 = {acc[i][j][0], acc[i][j][1]};
            float2 o2 = {acc[i][j][2], acc[i][j][3]};
            *(float2*)&ctx[((size_t)(b_ * SEQ) + r1) * DM + h * HD + d] = o1;
            *(float2*)&ctx[((size_t)(b_ * SEQ) + r2) * DM + h * HD + d] = o2;
        }
    }
}

// ===========================================================================
// LayerNorm
// ===========================================================================
__global__ void __launch_bounds__(256)
layernorm_rows(const float* __restrict__ pre, const float* __restrict__ g,
               const float* __restrict__ be, float* __restrict__ out)
{
    int warp = threadIdx.x >> 5, lane = threadIdx.x & 31;
    size_t row = (size_t)blockIdx.x * 8 + warp;
    const float* p = pre + row * DM;

    float x[16];
    float s = 0.f, s2 = 0.f;
#pragma unroll
    for (int i = 0; i < 4; i++) {
        float4 v = *(const float4*)(p + i * 128 + lane * 4);
        x[i * 4 + 0] = v.x; x[i * 4 + 1] = v.y;
        x[i * 4 + 2] = v.z; x[i * 4 + 3] = v.w;
        s  += v.x + v.y + v.z + v.w;
        s2 += v.x * v.x + v.y * v.y + v.z * v.z + v.w * v.w;
    }
#pragma unroll
    for (int o = 16; o; o >>= 1) {
        s  += __shfl_xor_sync(0xffffffffu, s,  o);
        s2 += __shfl_xor_sync(0xffffffffu, s2, o);
    }
    float mu  = s  * (1.f / DM);
    float var = s2 * (1.f / DM) - mu * mu;
    float inv = rsqrtf(var + 1e-6f);

    float* po = out + row * DM;
#pragma unroll
    for (int i = 0; i < 4; i++) {
        float4 w;
        int c = i * 128 + lane * 4;
        w.x = (x[i * 4 + 0] - mu) * inv * g[c + 0] + be[c + 0];
        w.y = (x[i * 4 + 1] - mu) * inv * g[c + 1] + be[c + 1];
        w.z = (x[i * 4 + 2] - mu) * inv * g[c + 2] + be[c + 2];
        w.w = (x[i * 4 + 3] - mu) * inv * g[c + 3] + be[c + 3];
        *(float4*)(po + c) = w;
    }
}

// ---------------------------------------------------------------------------
// Launch
// ---------------------------------------------------------------------------
extern "C" void kernel_launch(void* const* d_in, const int* in_sizes, int n_in,
                              void* d_out, int out_size)
{
    const float* Q   = (const float*)d_in[0];
    const float* K   = (const float*)d_in[1];
    const float* V   = (const float*)d_in[2];
    const int*   mask = (const int*)d_in[3];
    const float* adjoin = (const float*)d_in[4];
    const float* Wq = (const float*)d_in[5];
    const float* bq = (const float*)d_in[6];
    const float* Wk = (const float*)d_in[7];
    const float* bk = (const float*)d_in[8];
    const float* Wv = (const float*)d_in[9];
    const float* bv = (const float*)d_in[10];
    const float* Wo = (const float*)d_in[11];
    const float* bo = (const float*)d_in[12];
    const float* lg = (const float*)d_in[13];
    const float* lb = (const float*)d_in[14];

    float *cb, *pb, *afb;
    cudaGetSymbolAddress((void**)&cb,  g_ctx);
    cudaGetSymbolAddress((void**)&pb,  g_pre);
    cudaGetSymbolAddress((void**)&afb, g_attn_fb);

    __nv_bfloat16 *xh, *xl, *wh, *wl, *qh, *ql, *kh, *kl, *vh, *vl, *ph;
    cudaGetSymbolAddress((void**)&xh, g_xh);
    cudaGetSymbolAddress((void**)&xl, g_xl);
    cudaGetSymbolAddress((void**)&wh, g_wh);
    cudaGetSymbolAddress((void**)&wl, g_wl);
    cudaGetSymbolAddress((void**)&qh, g_qh);
    cudaGetSymbolAddress((void**)&ql, g_ql);
    cudaGetSymbolAddress((void**)&kh, g_kh);
    cudaGetSymbolAddress((void**)&kl, g_kl);
    cudaGetSymbolAddress((void**)&vh, g_vh);
    cudaGetSymbolAddress((void**)&vl, g_vl);
    cudaGetSymbolAddress((void**)&ph, g_ph);
    const size_t WSZ = (size_t)DM * DM;

    float* out0 = (float*)d_out;
    const size_t OUT0 = (size_t)BSZ * SEQ * DM;
    const size_t ATTN = (size_t)BSZ * NH * SEQ * SEQ;
    float* attn = ((size_t)out_size >= OUT0 + ATTN) ? (out0 + OUT0) : afb;

    static int attr_set = 0;
    if (!attr_set) {
        cudaFuncSetAttribute(gemm_proj_mma3<0>,
                             cudaFuncAttributeMaxDynamicSharedMemorySize, PROJ_SMEM);
        cudaFuncSetAttribute(gemm_proj_mma3<1>,
                             cudaFuncAttributeMaxDynamicSharedMemorySize, PROJ_SMEM);
        cudaFuncSetAttribute(gemm_proj_mma3<2>,
                             cudaFuncAttributeMaxDynamicSharedMemorySize, PROJ_SMEM);
        cudaFuncSetAttribute(gemm_scores_mma,
                             cudaFuncAttributeMaxDynamicSharedMemorySize, SCM_SMEM);
        attr_set = 1;
    }

    dim3 wgrid(DM / 32, DM / 32), wblk(32, 8);
    const int XBLK = (int)(((size_t)BSZ * SEQ * DM) / 4 / 256);   // 4096
    dim3 gp(DM / 128, (BSZ * SEQ) / 128);   // (4, 64)

    // 0) Weights -> [n][k] bf16 hi/lo
    convert_w<<<wgrid, wblk>>>(Wq, wh + 0 * WSZ, wl + 0 * WSZ);
    convert_w<<<wgrid, wblk>>>(Wk, wh + 1 * WSZ, wl + 1 * WSZ);
    convert_w<<<wgrid, wblk>>>(Wv, wh + 2 * WSZ, wl + 2 * WSZ);
    convert_w<<<wgrid, wblk>>>(Wo, wh + 3 * WSZ, wl + 3 * WSZ);

    // 1) Projections -> bf16 split q/k [b,h,s,d], v [b,h,d,s]
    convert_x<<<XBLK, 256>>>(Q, xh, xl);
    gemm_proj_mma3<0><<<gp, 256, PROJ_SMEM>>>(xh, xl, wh + 0 * WSZ, wl + 0 * WSZ,
                                              bq, nullptr, nullptr, qh, ql);
    convert_x<<<XBLK, 256>>>(K, xh, xl);
    gemm_proj_mma3<0><<<gp, 256, PROJ_SMEM>>>(xh, xl, wh + 1 * WSZ, wl + 1 * WSZ,
                                              bk, nullptr, nullptr, kh, kl);
    convert_x<<<XBLK, 256>>>(V, xh, xl);
    gemm_proj_mma3<1><<<gp, 256, PROJ_SMEM>>>(xh, xl, wh + 2 * WSZ, wl + 2 * WSZ,
                                              bv, nullptr, nullptr, vh, vl);

    // 2) Scores (MMA) + scale + mask + adjoin
    dim3 gs(SEQ / 128, SEQ / 128, BSZ * NH);
    gemm_scores_mma<<<gs, 256, SCM_SMEM>>>(qh, ql, kh, kl, mask, adjoin, attn);

    // 3) Softmax (fp32 attn + bf16 P)
    softmax_rows<<<(BSZ * NH * SEQ) / 8, 256>>>(attn, ph);

    // 4) Context (MMA)
    dim3 gc(SEQ / 128, BSZ * NH);
    gemm_ctx_mma<<<gc, 256>>>(ph, vh, vl, cb);

    // 5) Output projection + bias + residual(Q)
    convert_x<<<XBLK, 256>>>(cb, xh, xl);
    gemm_proj_mma3<2><<<gp, 256, PROJ_SMEM>>>(xh, xl, wh + 3 * WSZ, wl + 3 * WSZ,
                                              bo, Q, pb, nullptr, nullptr);

    // 6) LayerNorm -> out
    layernorm_rows<<<(BSZ * SEQ) / 8, 256>>>(pb, lg, lb, out0);
}